// round 1
// baseline (speedup 1.0000x reference)
#include <cuda_runtime.h>
#include <math.h>

#define NM     64      // number of matrices (B*H)
#define MATN   128     // matrix dim (D)
#define SLEN   2048    // sequence length
#define RANK   64
#define SWEEPS 9
#define ROUNDS 127     // MATN - 1
#define LDA    129     // padded shared stride

// Scratch (device globals; no allocations allowed)
__device__ float g_G2[2][NM][MATN][MATN];   // partial Gram matrices (8 MB)
__device__ float g_P[NM][MATN][MATN];       // projectors (4 MB)

// Chess-tournament pairing: round rr in [0,127), pair index i in [0,64)
__device__ __forceinline__ void pair_pq(int i, int rr, int& p, int& q) {
    if (i == 0) { p = 0; }
    else { int x = i - 1 + rr; if (x >= 127) x -= 127; p = 1 + x; }
    int y = 126 - i + rr; if (y >= 127) y -= 127; q = 1 + y;
}

// ---------------------------------------------------------------------------
// Kernel 1: partial Gram  G_half = X_halfᵀ X_half   (grid: NM x 2, 256 thr)
// ---------------------------------------------------------------------------
__global__ __launch_bounds__(256) void gram_kernel(const float* __restrict__ X) {
    __shared__ float Xs[64][MATN];
    const int m = blockIdx.x, half = blockIdx.y;
    const int t = threadIdx.x;
    const int a0 = (t >> 4) * 8, b0 = (t & 15) * 8;
    float acc[8][8];
#pragma unroll
    for (int i = 0; i < 8; i++)
#pragma unroll
        for (int j = 0; j < 8; j++) acc[i][j] = 0.f;

    const float* Xm = X + ((size_t)m * SLEN + (size_t)half * 1024) * MATN;
    for (int ch = 0; ch < 16; ch++) {
        const float4* src = (const float4*)(Xm + (size_t)ch * 64 * MATN);
        float4* dst = (float4*)&Xs[0][0];
#pragma unroll
        for (int j = 0; j < 8; j++) dst[t + 256 * j] = src[t + 256 * j];
        __syncthreads();
#pragma unroll 4
        for (int s = 0; s < 64; s++) {
            float4 a40 = *(const float4*)&Xs[s][a0];
            float4 a41 = *(const float4*)&Xs[s][a0 + 4];
            float4 b40 = *(const float4*)&Xs[s][b0];
            float4 b41 = *(const float4*)&Xs[s][b0 + 4];
            float av[8] = {a40.x, a40.y, a40.z, a40.w, a41.x, a41.y, a41.z, a41.w};
            float bv[8] = {b40.x, b40.y, b40.z, b40.w, b41.x, b41.y, b41.z, b41.w};
#pragma unroll
            for (int i = 0; i < 8; i++)
#pragma unroll
                for (int j = 0; j < 8; j++) acc[i][j] += av[i] * bv[j];
        }
        __syncthreads();
    }
    float* Gp = &g_G2[half][m][0][0];
#pragma unroll
    for (int i = 0; i < 8; i++) {
        float4 v0 = {acc[i][0], acc[i][1], acc[i][2], acc[i][3]};
        float4 v1 = {acc[i][4], acc[i][5], acc[i][6], acc[i][7]};
        *(float4*)&Gp[(a0 + i) * MATN + b0] = v0;
        *(float4*)&Gp[(a0 + i) * MATN + b0 + 4] = v1;
    }
}

// ---------------------------------------------------------------------------
// Kernel 2: Jacobi eigensolver per matrix + projector build
// grid: NM, 256 threads, dynamic smem = A(128x129) + V(128x129) + extras
// ---------------------------------------------------------------------------
#define JAC_SMEM ((2 * MATN * LDA + 64 + 64 + MATN + MATN + 64) * 4)

__global__ __launch_bounds__(256) void jacobi_kernel() {
    extern __shared__ float sm[];
    float* A   = sm;
    float* V   = sm + MATN * LDA;
    float* csc = V + MATN * LDA;
    float* css = csc + 64;
    float* ev  = css + 64;
    float* msk = ev + MATN;
    int*   sidx = (int*)(msk + MATN);

    const int m = blockIdx.x, t = threadIdx.x;

    // Load A = G (sum of two halves), V = I
    for (int idx = t; idx < MATN * MATN; idx += 256) {
        int i = idx >> 7, j = idx & 127;
        A[i * LDA + j] = g_G2[0][m][i][j] + g_G2[1][m][i][j];
        V[i * LDA + j] = (i == j) ? 1.f : 0.f;
    }
    __syncthreads();

    const int ap = t >> 2;     // this thread's fixed row-pair index
    const int brem = t & 3;

    for (int r = 0; r < SWEEPS * ROUNDS; r++) {
        const int rr = r - (r / ROUNDS) * ROUNDS;   // r % 127

        // Phase 0: rotation angles for the 64 disjoint pairs
        if (t < 64) {
            int p, q; pair_pq(t, rr, p, q);
            float app = A[p * LDA + p], aqq = A[q * LDA + q], apq = A[p * LDA + q];
            float c = 1.f, s = 0.f;
            float scl = fabsf(app) + fabsf(aqq);
            if (fabsf(apq) > 1e-12f * scl + 1e-38f) {
                float tau = (aqq - app) / (2.f * apq);
                float tt = 1.f / (fabsf(tau) + sqrtf(1.f + tau * tau));
                tt = (tau < 0.f) ? -tt : tt;
                c = rsqrtf(1.f + tt * tt);
                s = tt * c;
            }
            csc[t] = c; css[t] = s;
        }
        __syncthreads();

        // Phase 1: fused 2x2 closure-block update A' = JᵀAJ (hazard-free:
        // each thread owns disjoint element sets), plus V = V·J.
        int pa, qa; pair_pq(ap, rr, pa, qa);
        const float ca = csc[ap], sa = css[ap];
#pragma unroll
        for (int k = 0; k < 16; k++) {
            int bp = brem + (k << 2);
            int pb, qb; pair_pq(bp, rr, pb, qb);
            float cb = csc[bp], sb = css[bp];
            float m00 = A[pa * LDA + pb], m01 = A[pa * LDA + qb];
            float m10 = A[qa * LDA + pb], m11 = A[qa * LDA + qb];
            float r00 = ca * m00 - sa * m10, r01 = ca * m01 - sa * m11;
            float r10 = sa * m00 + ca * m10, r11 = sa * m01 + ca * m11;
            A[pa * LDA + pb] = cb * r00 - sb * r01;
            A[pa * LDA + qb] = sb * r00 + cb * r01;
            A[qa * LDA + pb] = cb * r10 - sb * r11;
            A[qa * LDA + qb] = sb * r10 + cb * r11;
        }
#pragma unroll
        for (int k = 0; k < 32; k++) {
            int row = brem + (k << 2);
            float v0 = V[row * LDA + pa], v1 = V[row * LDA + qa];
            V[row * LDA + pa] = ca * v0 - sa * v1;
            V[row * LDA + qa] = sa * v0 + ca * v1;
        }
        __syncthreads();
    }

    // Eigenvalues + top-RANK selection (tie-break by index -> deterministic)
    if (t < MATN) ev[t] = A[t * LDA + t];
    __syncthreads();
    if (t < MATN) {
        float e = ev[t]; int rk = 0;
        for (int j = 0; j < MATN; j++) {
            float o = ev[j];
            if (o > e || (o == e && j < t)) rk++;
        }
        msk[t] = (rk < RANK) ? 1.f : 0.f;
        if (rk < RANK) sidx[rk] = t;
    }
    __syncthreads();

    // P = V_sel V_selᵀ  (loop only the 64 selected eigenvector columns)
    const int a0 = (t >> 4) * 8, b0 = (t & 15) * 8;
    float acc[8][8];
#pragma unroll
    for (int i = 0; i < 8; i++)
#pragma unroll
        for (int j = 0; j < 8; j++) acc[i][j] = 0.f;

    for (int ii = 0; ii < RANK; ii++) {
        int col = sidx[ii];
        float va[8], vb[8];
#pragma unroll
        for (int k = 0; k < 8; k++) va[k] = V[(a0 + k) * LDA + col];
#pragma unroll
        for (int k = 0; k < 8; k++) vb[k] = V[(b0 + k) * LDA + col];
#pragma unroll
        for (int i = 0; i < 8; i++)
#pragma unroll
            for (int j = 0; j < 8; j++) acc[i][j] += va[i] * vb[j];
    }
    float* Pp = &g_P[m][0][0];
#pragma unroll
    for (int i = 0; i < 8; i++) {
        float4 v0 = {acc[i][0], acc[i][1], acc[i][2], acc[i][3]};
        float4 v1 = {acc[i][4], acc[i][5], acc[i][6], acc[i][7]};
        *(float4*)&Pp[(a0 + i) * MATN + b0] = v0;
        *(float4*)&Pp[(a0 + i) * MATN + b0 + 4] = v1;
    }
}

// ---------------------------------------------------------------------------
// Kernel 3: Y = X · P  (grid: NM x 32 row-blocks of 64 rows, 256 threads)
// ---------------------------------------------------------------------------
#define REC_SMEM ((64 * LDA + MATN * MATN) * 4)

__global__ __launch_bounds__(256) void recon_kernel(const float* __restrict__ X,
                                                    float* __restrict__ out) {
    extern __shared__ float sm[];
    float* Xs = sm;              // 64 x 129
    float* Ps = sm + 64 * LDA;   // 128 x 128
    const int m = blockIdx.x, rb = blockIdx.y;
    const int t = threadIdx.x;

    const float* Xm = X + ((size_t)m * SLEN + (size_t)rb * 64) * MATN;
    for (int idx = t; idx < 64 * MATN; idx += 256) {
        int rI = idx >> 7, c = idx & 127;
        Xs[rI * LDA + c] = Xm[idx];
    }
    const float4* Pg = (const float4*)&g_P[m][0][0];
    float4* Pd = (float4*)Ps;
    for (int idx = t; idx < MATN * MATN / 4; idx += 256) Pd[idx] = Pg[idx];
    __syncthreads();

    const int r0 = (t >> 4) * 4, c0 = (t & 15) * 8;
    float acc[4][8];
#pragma unroll
    for (int i = 0; i < 4; i++)
#pragma unroll
        for (int j = 0; j < 8; j++) acc[i][j] = 0.f;

    for (int k = 0; k < MATN; k++) {
        float xv[4];
#pragma unroll
        for (int i = 0; i < 4; i++) xv[i] = Xs[(r0 + i) * LDA + k];
        float4 p0 = *(const float4*)&Ps[k * MATN + c0];
        float4 p1 = *(const float4*)&Ps[k * MATN + c0 + 4];
        float pv[8] = {p0.x, p0.y, p0.z, p0.w, p1.x, p1.y, p1.z, p1.w};
#pragma unroll
        for (int i = 0; i < 4; i++)
#pragma unroll
            for (int j = 0; j < 8; j++) acc[i][j] += xv[i] * pv[j];
    }

    float* Om = out + ((size_t)m * SLEN + (size_t)rb * 64) * MATN;
#pragma unroll
    for (int i = 0; i < 4; i++) {
        float4 v0 = {acc[i][0], acc[i][1], acc[i][2], acc[i][3]};
        float4 v1 = {acc[i][4], acc[i][5], acc[i][6], acc[i][7]};
        *(float4*)&Om[(r0 + i) * MATN + c0] = v0;
        *(float4*)&Om[(r0 + i) * MATN + c0 + 4] = v1;
    }
}

// ---------------------------------------------------------------------------
extern "C" void kernel_launch(void* const* d_in, const int* in_sizes, int n_in,
                              void* d_out, int out_size) {
    const float* X = (const float*)d_in[0];   // kv_cache fp32 (4,16,2048,128)
    float* out = (float*)d_out;               // fp32, same shape

    // Idempotent attribute opt-ins (>48KB dynamic smem)
    cudaFuncSetAttribute(jacobi_kernel, cudaFuncAttributeMaxDynamicSharedMemorySize, JAC_SMEM);
    cudaFuncSetAttribute(recon_kernel,  cudaFuncAttributeMaxDynamicSharedMemorySize, REC_SMEM);

    gram_kernel<<<dim3(NM, 2), 256>>>(X);
    jacobi_kernel<<<NM, 256, JAC_SMEM>>>();
    recon_kernel<<<dim3(NM, 32), 256, REC_SMEM>>>(X, out);
}

// round 2
// speedup vs baseline: 1.1176x; 1.1176x over previous
#include <cuda_runtime.h>
#include <math.h>

#define NM     64      // number of matrices (B*H)
#define MATN   128     // matrix dim (D)
#define SLEN   2048    // sequence length
#define RANK   64
#define SWEEPS 8
#define ROUNDS 127     // MATN - 1
#define LDA    129     // padded shared stride for A (scalar access)
#define NPART  4       // gram split-K parts

// Scratch (device globals; no allocations allowed)
__device__ float g_G4[NPART][NM][MATN][MATN];  // partial Gram matrices (16 MB)
__device__ float g_P[NM][MATN][MATN];          // projectors (4 MB)

// Chess-tournament pairing: round rr in [0,127), pair index i in [0,64)
__device__ __forceinline__ void pair_pq(int i, int rr, int& p, int& q) {
    if (i == 0) { p = 0; }
    else { int x = i - 1 + rr; if (x >= 127) x -= 127; p = 1 + x; }
    int y = 126 - i + rr; if (y >= 127) y -= 127; q = 1 + y;
}

// ---------------------------------------------------------------------------
// Kernel 1: partial Gram  G_part = X_partᵀ X_part   (grid: NM x NPART, 256 thr)
// ---------------------------------------------------------------------------
__global__ __launch_bounds__(256) void gram_kernel(const float* __restrict__ X) {
    __shared__ float Xs[64][MATN];
    const int m = blockIdx.x, part = blockIdx.y;
    const int t = threadIdx.x;
    const int a0 = (t >> 4) * 8, b0 = (t & 15) * 8;
    float acc[8][8];
#pragma unroll
    for (int i = 0; i < 8; i++)
#pragma unroll
        for (int j = 0; j < 8; j++) acc[i][j] = 0.f;

    const float* Xm = X + ((size_t)m * SLEN + (size_t)part * 512) * MATN;
    for (int ch = 0; ch < 8; ch++) {
        const float4* src = (const float4*)(Xm + (size_t)ch * 64 * MATN);
        float4* dst = (float4*)&Xs[0][0];
#pragma unroll
        for (int j = 0; j < 8; j++) dst[t + 256 * j] = src[t + 256 * j];
        __syncthreads();
#pragma unroll 4
        for (int s = 0; s < 64; s++) {
            float4 a40 = *(const float4*)&Xs[s][a0];
            float4 a41 = *(const float4*)&Xs[s][a0 + 4];
            float4 b40 = *(const float4*)&Xs[s][b0];
            float4 b41 = *(const float4*)&Xs[s][b0 + 4];
            float av[8] = {a40.x, a40.y, a40.z, a40.w, a41.x, a41.y, a41.z, a41.w};
            float bv[8] = {b40.x, b40.y, b40.z, b40.w, b41.x, b41.y, b41.z, b41.w};
#pragma unroll
            for (int i = 0; i < 8; i++)
#pragma unroll
                for (int j = 0; j < 8; j++) acc[i][j] += av[i] * bv[j];
        }
        __syncthreads();
    }
    float* Gp = &g_G4[part][m][0][0];
#pragma unroll
    for (int i = 0; i < 8; i++) {
        float4 v0 = {acc[i][0], acc[i][1], acc[i][2], acc[i][3]};
        float4 v1 = {acc[i][4], acc[i][5], acc[i][6], acc[i][7]};
        *(float4*)&Gp[(a0 + i) * MATN + b0] = v0;
        *(float4*)&Gp[(a0 + i) * MATN + b0 + 4] = v1;
    }
}

// ---------------------------------------------------------------------------
// Kernel 2: Jacobi eigensolver per matrix + projector build
// grid: NM, 512 threads, dynamic smem layout:
//   rot[64] float4 | A[128*129] | W[128*128] (W = Vᵀ) | ev[128] | sidx[64]
// ---------------------------------------------------------------------------
#define JAC_SMEM ((64 * 4 + MATN * LDA + MATN * MATN + MATN + 64) * 4)

__global__ __launch_bounds__(512) void jacobi_kernel() {
    extern __shared__ float sm[];
    float4* rot = (float4*)sm;                 // 64 float4 (c, s, p, q)
    float*  A   = sm + 64 * 4;                 // 128 x 129
    float*  W   = A + MATN * LDA;              // 128 x 128 (rows = eigvecs)
    float*  ev  = W + MATN * MATN;             // 128
    int*    sidx = (int*)(ev + MATN);          // 64

    const int m = blockIdx.x, t = threadIdx.x;

    // Load A = sum of 4 Gram partials, W = I
    for (int idx = t; idx < MATN * MATN; idx += 512) {
        int i = idx >> 7, j = idx & 127;
        A[i * LDA + j] = g_G4[0][m][i][j] + g_G4[1][m][i][j]
                       + g_G4[2][m][i][j] + g_G4[3][m][i][j];
        W[idx] = (i == j) ? 1.f : 0.f;
    }
    __syncthreads();

    const int pa  = t >> 3;   // this thread's fixed pair index (0..63)
    const int sub = t & 7;    // sub-slot (0..7)

    for (int r = 0; r < SWEEPS * ROUNDS; r++) {
        const int rr = r - (r / ROUNDS) * ROUNDS;   // r % 127

        // Phase 0: rotation angles + pair LUT for the 64 disjoint pairs
        if (t < 64) {
            int p, q; pair_pq(t, rr, p, q);
            float app = A[p * LDA + p], aqq = A[q * LDA + q], apq = A[p * LDA + q];
            float c = 1.f, s = 0.f;
            float scl = fabsf(app) + fabsf(aqq);
            if (fabsf(apq) > 1e-12f * scl + 1e-38f) {
                float tau = (aqq - app) / (2.f * apq);
                float tt = 1.f / (fabsf(tau) + sqrtf(1.f + tau * tau));
                tt = (tau < 0.f) ? -tt : tt;
                c = rsqrtf(1.f + tt * tt);
                s = tt * c;
            }
            rot[t] = make_float4(c, s, __int_as_float(p), __int_as_float(q));
        }
        __syncthreads();

        float4 ra = rot[pa];
        const float ca = ra.x, sa = ra.y;
        const int p_a = __float_as_int(ra.z), q_a = __float_as_int(ra.w);
        const float* Arp = A + p_a * LDA;
        const float* Arq = A + q_a * LDA;

        // Phase 1a: fused 2x2 closure-block update A' = JᵀAJ
        // (each thread owns rows {p_a,q_a} x this sub's 8 column-pairs)
#pragma unroll
        for (int k = 0; k < 8; k++) {
            int bp = sub + (k << 3);
            float4 rb = rot[bp];
            float cb = rb.x, sb = rb.y;
            int p_b = __float_as_int(rb.z), q_b = __float_as_int(rb.w);
            float m00 = Arp[p_b], m01 = Arp[q_b];
            float m10 = Arq[p_b], m11 = Arq[q_b];
            float r00 = ca * m00 - sa * m10, r01 = ca * m01 - sa * m11;
            float r10 = sa * m00 + ca * m10, r11 = sa * m01 + ca * m11;
            A[p_a * LDA + p_b] = cb * r00 - sb * r01;
            A[p_a * LDA + q_b] = sb * r00 + cb * r01;
            A[q_a * LDA + p_b] = cb * r10 - sb * r11;
            A[q_a * LDA + q_b] = sb * r10 + cb * r11;
        }

        // Phase 1b: W = Vᵀ row rotation (contiguous, float4)
        {
            float4* Wp = (float4*)(W + p_a * MATN + (sub << 4));
            float4* Wq = (float4*)(W + q_a * MATN + (sub << 4));
#pragma unroll
            for (int i = 0; i < 4; i++) {
                float4 x = Wp[i], y = Wq[i];
                float4 nx, ny;
                nx.x = ca * x.x - sa * y.x;  ny.x = sa * x.x + ca * y.x;
                nx.y = ca * x.y - sa * y.y;  ny.y = sa * x.y + ca * y.y;
                nx.z = ca * x.z - sa * y.z;  ny.z = sa * x.z + ca * y.z;
                nx.w = ca * x.w - sa * y.w;  ny.w = sa * x.w + ca * y.w;
                Wp[i] = nx; Wq[i] = ny;
            }
        }
        __syncthreads();
    }

    // Eigenvalues + top-RANK selection (tie-break by index -> deterministic)
    if (t < MATN) ev[t] = A[t * LDA + t];
    __syncthreads();
    if (t < MATN) {
        float e = ev[t]; int rk = 0;
        for (int j = 0; j < MATN; j++) {
            float o = ev[j];
            if (o > e || (o == e && j < t)) rk++;
        }
        if (rk < RANK) sidx[rk] = t;
    }
    __syncthreads();

    // P = V_sel V_selᵀ = Σ_r W[r,:]ᵀ W[r,:] over the 64 selected rows of W
    const int i0 = (t >> 5) * 8, j0 = (t & 31) * 4;
    float acc[8][4];
#pragma unroll
    for (int i = 0; i < 8; i++)
#pragma unroll
        for (int j = 0; j < 4; j++) acc[i][j] = 0.f;

    for (int ii = 0; ii < RANK; ii++) {
        int row = sidx[ii];
        const float* Wr = W + row * MATN;
        float4 va0 = *(const float4*)&Wr[i0];
        float4 va1 = *(const float4*)&Wr[i0 + 4];
        float4 vb  = *(const float4*)&Wr[j0];
        float va[8] = {va0.x, va0.y, va0.z, va0.w, va1.x, va1.y, va1.z, va1.w};
        float vbv[4] = {vb.x, vb.y, vb.z, vb.w};
#pragma unroll
        for (int i = 0; i < 8; i++)
#pragma unroll
            for (int j = 0; j < 4; j++) acc[i][j] += va[i] * vbv[j];
    }
    float* Pp = &g_P[m][0][0];
#pragma unroll
    for (int i = 0; i < 8; i++) {
        float4 v = {acc[i][0], acc[i][1], acc[i][2], acc[i][3]};
        *(float4*)&Pp[(i0 + i) * MATN + j0] = v;
    }
}

// ---------------------------------------------------------------------------
// Kernel 3: Y = X · P  (grid: NM x 32 row-blocks of 64 rows, 256 threads)
// ---------------------------------------------------------------------------
#define REC_SMEM ((64 * LDA + MATN * MATN) * 4)

__global__ __launch_bounds__(256) void recon_kernel(const float* __restrict__ X,
                                                    float* __restrict__ out) {
    extern __shared__ float sm[];
    float* Xs = sm;              // 64 x 129
    float* Ps = sm + 64 * LDA;   // 128 x 128
    const int m = blockIdx.x, rb = blockIdx.y;
    const int t = threadIdx.x;

    const float* Xm = X + ((size_t)m * SLEN + (size_t)rb * 64) * MATN;
    for (int idx = t; idx < 64 * MATN; idx += 256) {
        int rI = idx >> 7, c = idx & 127;
        Xs[rI * LDA + c] = Xm[idx];
    }
    const float4* Pg = (const float4*)&g_P[m][0][0];
    float4* Pd = (float4*)Ps;
    for (int idx = t; idx < MATN * MATN / 4; idx += 256) Pd[idx] = Pg[idx];
    __syncthreads();

    const int r0 = (t >> 4) * 4, c0 = (t & 15) * 8;
    float acc[4][8];
#pragma unroll
    for (int i = 0; i < 4; i++)
#pragma unroll
        for (int j = 0; j < 8; j++) acc[i][j] = 0.f;

    for (int k = 0; k < MATN; k++) {
        float xv[4];
#pragma unroll
        for (int i = 0; i < 4; i++) xv[i] = Xs[(r0 + i) * LDA + k];
        float4 p0 = *(const float4*)&Ps[k * MATN + c0];
        float4 p1 = *(const float4*)&Ps[k * MATN + c0 + 4];
        float pv[8] = {p0.x, p0.y, p0.z, p0.w, p1.x, p1.y, p1.z, p1.w};
#pragma unroll
        for (int i = 0; i < 4; i++)
#pragma unroll
            for (int j = 0; j < 8; j++) acc[i][j] += xv[i] * pv[j];
    }

    float* Om = out + ((size_t)m * SLEN + (size_t)rb * 64) * MATN;
#pragma unroll
    for (int i = 0; i < 4; i++) {
        float4 v0 = {acc[i][0], acc[i][1], acc[i][2], acc[i][3]};
        float4 v1 = {acc[i][4], acc[i][5], acc[i][6], acc[i][7]};
        *(float4*)&Om[(r0 + i) * MATN + c0] = v0;
        *(float4*)&Om[(r0 + i) * MATN + c0 + 4] = v1;
    }
}

// ---------------------------------------------------------------------------
extern "C" void kernel_launch(void* const* d_in, const int* in_sizes, int n_in,
                              void* d_out, int out_size) {
    const float* X = (const float*)d_in[0];   // kv_cache fp32 (4,16,2048,128)
    float* out = (float*)d_out;               // fp32, same shape

    cudaFuncSetAttribute(jacobi_kernel, cudaFuncAttributeMaxDynamicSharedMemorySize, JAC_SMEM);
    cudaFuncSetAttribute(recon_kernel,  cudaFuncAttributeMaxDynamicSharedMemorySize, REC_SMEM);

    gram_kernel<<<dim3(NM, NPART), 256>>>(X);
    jacobi_kernel<<<NM, 512, JAC_SMEM>>>();
    recon_kernel<<<dim3(NM, 32), 256, REC_SMEM>>>(X, out);
}

// round 3
// speedup vs baseline: 1.7614x; 1.5760x over previous
#include <cuda_runtime.h>
#include <math.h>

#define NM     64      // number of matrices (B*H)
#define MATN   128     // matrix dim (D)
#define SLEN   2048    // sequence length
#define RANK   64
#define SWEEPS 7
#define ROUNDS 127     // MATN - 1
#define LDA    136     // padded shared stride for A  (136 % 32 == 8 -> conflict-free tiles)
#define LDW    132     // padded shared stride for W  (132 % 32 == 4 -> conflict-free float4)
#define NPART  4       // gram split-K parts

// Scratch (device globals; no allocations allowed)
__device__ float g_G4[NPART][NM][MATN][MATN];  // partial Gram matrices (16 MB)
__device__ float g_P[NM][MATN][MATN];          // projectors (4 MB)

typedef unsigned long long u64t;
__device__ __forceinline__ u64t pack2(float lo, float hi) {
    u64t r; asm("mov.b64 %0,{%1,%2};" : "=l"(r) : "f"(lo), "f"(hi)); return r;
}
__device__ __forceinline__ u64t mul2(u64t a, u64t b) {
    u64t r; asm("mul.rn.f32x2 %0,%1,%2;" : "=l"(r) : "l"(a), "l"(b)); return r;
}
__device__ __forceinline__ u64t fma2(u64t a, u64t b, u64t c) {
    u64t r; asm("fma.rn.f32x2 %0,%1,%2,%3;" : "=l"(r) : "l"(a), "l"(b), "l"(c)); return r;
}

// Chess-tournament pairing: round rr in [0,127), pair index i in [0,64)
__device__ __forceinline__ void pair_pq(int i, int rr, int& p, int& q) {
    if (i == 0) { p = 0; }
    else { int x = i - 1 + rr; if (x >= 127) x -= 127; p = 1 + x; }
    int y = 126 - i + rr; if (y >= 127) y -= 127; q = 1 + y;
}

// ---------------------------------------------------------------------------
// Kernel 1: partial Gram  G_part = X_partᵀ X_part   (grid: NM x NPART, 256 thr)
// ---------------------------------------------------------------------------
__global__ __launch_bounds__(256) void gram_kernel(const float* __restrict__ X) {
    __shared__ float Xs[64][MATN];
    const int m = blockIdx.x, part = blockIdx.y;
    const int t = threadIdx.x;
    const int a0 = (t >> 4) * 8, b0 = (t & 15) * 8;
    float acc[8][8];
#pragma unroll
    for (int i = 0; i < 8; i++)
#pragma unroll
        for (int j = 0; j < 8; j++) acc[i][j] = 0.f;

    const float* Xm = X + ((size_t)m * SLEN + (size_t)part * 512) * MATN;
    for (int ch = 0; ch < 8; ch++) {
        const float4* src = (const float4*)(Xm + (size_t)ch * 64 * MATN);
        float4* dst = (float4*)&Xs[0][0];
#pragma unroll
        for (int j = 0; j < 8; j++) dst[t + 256 * j] = src[t + 256 * j];
        __syncthreads();
#pragma unroll 4
        for (int s = 0; s < 64; s++) {
            float4 a40 = *(const float4*)&Xs[s][a0];
            float4 a41 = *(const float4*)&Xs[s][a0 + 4];
            float4 b40 = *(const float4*)&Xs[s][b0];
            float4 b41 = *(const float4*)&Xs[s][b0 + 4];
            float av[8] = {a40.x, a40.y, a40.z, a40.w, a41.x, a41.y, a41.z, a41.w};
            float bv[8] = {b40.x, b40.y, b40.z, b40.w, b41.x, b41.y, b41.z, b41.w};
#pragma unroll
            for (int i = 0; i < 8; i++)
#pragma unroll
                for (int j = 0; j < 8; j++) acc[i][j] += av[i] * bv[j];
        }
        __syncthreads();
    }
    float* Gp = &g_G4[part][m][0][0];
#pragma unroll
    for (int i = 0; i < 8; i++) {
        float4 v0 = {acc[i][0], acc[i][1], acc[i][2], acc[i][3]};
        float4 v1 = {acc[i][4], acc[i][5], acc[i][6], acc[i][7]};
        *(float4*)&Gp[(a0 + i) * MATN + b0] = v0;
        *(float4*)&Gp[(a0 + i) * MATN + b0 + 4] = v1;
    }
}

// ---------------------------------------------------------------------------
// Kernel 2: Jacobi eigensolver per matrix + projector build
// grid: NM, 512 threads, dynamic smem layout:
//   rot[64] float4 | A[128*136] | W[128*132] (W = Vᵀ) | ev[128] | sidx[64]
// ---------------------------------------------------------------------------
#define JAC_SMEM ((64 * 4 + MATN * LDA + MATN * LDW + MATN + 64) * 4)

__global__ __launch_bounds__(512) void jacobi_kernel() {
    extern __shared__ float sm[];
    float4* rot = (float4*)sm;                 // 64 float4 (c, s, p, q)
    float*  A   = sm + 64 * 4;                 // 128 x 136
    float*  W   = A + MATN * LDA;              // 128 x 132 (rows = eigvecs)
    float*  ev  = W + MATN * LDW;              // 128
    int*    sidx = (int*)(ev + MATN);          // 64

    const int m = blockIdx.x, t = threadIdx.x;

    // Load A = sum of 4 Gram partials, W = I
    for (int idx = t; idx < MATN * MATN; idx += 512) {
        int i = idx >> 7, j = idx & 127;
        A[i * LDA + j] = g_G4[0][m][i][j] + g_G4[1][m][i][j]
                       + g_G4[2][m][i][j] + g_G4[3][m][i][j];
        W[i * LDW + j] = (i == j) ? 1.f : 0.f;
    }
    __syncthreads();

    const int pa  = t >> 3;   // this thread's fixed pair index (0..63)
    const int sub = t & 7;    // sub-slot (0..7)

    for (int r = 0; r < SWEEPS * ROUNDS; r++) {
        const int rr = r - (r / ROUNDS) * ROUNDS;   // r % 127

        // Phase 0: rotation angles + pair LUT for the 64 disjoint pairs
        if (t < 64) {
            int p, q; pair_pq(t, rr, p, q);
            float app = A[p * LDA + p], aqq = A[q * LDA + q], apq = A[p * LDA + q];
            float c = 1.f, s = 0.f;
            float scl = fabsf(app) + fabsf(aqq);
            if (fabsf(apq) > 1e-12f * scl + 1e-38f) {
                float tau = (aqq - app) / (2.f * apq);
                float tt = 1.f / (fabsf(tau) + sqrtf(1.f + tau * tau));
                tt = (tau < 0.f) ? -tt : tt;
                c = rsqrtf(1.f + tt * tt);
                s = tt * c;
            }
            rot[t] = make_float4(c, s, __int_as_float(p), __int_as_float(q));
        }
        __syncthreads();

        float4 ra = rot[pa];
        const float ca = ra.x, sa = ra.y;
        const int p_a = __float_as_int(ra.z), q_a = __float_as_int(ra.w);
        float* Arp = A + p_a * LDA;
        float* Arq = A + q_a * LDA;

        // Phase 1a: fused 2x2 closure-block update A' = JᵀAJ
        // (each thread owns rows {p_a,q_a} x this sub's 8 column-pairs;
        //  LDA=136 -> the warp's 4 rows x 8 consecutive cols are conflict-free)
#pragma unroll
        for (int k = 0; k < 8; k++) {
            int bp = sub + (k << 3);
            float4 rb = rot[bp];
            float cb = rb.x, sb = rb.y;
            int p_b = __float_as_int(rb.z), q_b = __float_as_int(rb.w);
            float m00 = Arp[p_b], m01 = Arp[q_b];
            float m10 = Arq[p_b], m11 = Arq[q_b];
            float r00 = ca * m00 - sa * m10, r01 = ca * m01 - sa * m11;
            float r10 = sa * m00 + ca * m10, r11 = sa * m01 + ca * m11;
            Arp[p_b] = cb * r00 - sb * r01;
            Arp[q_b] = sb * r00 + cb * r01;
            Arq[p_b] = cb * r10 - sb * r11;
            Arq[q_b] = sb * r10 + cb * r11;
        }

        // Phase 1b: W = Vᵀ row rotation, packed f32x2 (contiguous, 16B)
        {
            ulonglong2* Wp = (ulonglong2*)(W + p_a * LDW + (sub << 4));
            ulonglong2* Wq = (ulonglong2*)(W + q_a * LDW + (sub << 4));
            const u64t ca2  = pack2(ca, ca);
            const u64t sa2  = pack2(sa, sa);
            const u64t nsa2 = pack2(-sa, -sa);
#pragma unroll
            for (int i = 0; i < 4; i++) {
                ulonglong2 x = Wp[i], y = Wq[i];
                ulonglong2 nx, ny;
                nx.x = fma2(ca2, x.x, mul2(nsa2, y.x));
                nx.y = fma2(ca2, x.y, mul2(nsa2, y.y));
                ny.x = fma2(sa2, x.x, mul2(ca2, y.x));
                ny.y = fma2(sa2, x.y, mul2(ca2, y.y));
                Wp[i] = nx; Wq[i] = ny;
            }
        }
        __syncthreads();
    }

    // Eigenvalues + top-RANK selection (tie-break by index -> deterministic)
    if (t < MATN) ev[t] = A[t * LDA + t];
    __syncthreads();
    if (t < MATN) {
        float e = ev[t]; int rk = 0;
        for (int j = 0; j < MATN; j++) {
            float o = ev[j];
            if (o > e || (o == e && j < t)) rk++;
        }
        if (rk < RANK) sidx[rk] = t;
    }
    __syncthreads();

    // P = V_sel V_selᵀ = Σ_r W[r,:]ᵀ W[r,:] over the 64 selected rows of W
    const int i0 = (t >> 5) * 8, j0 = (t & 31) * 4;
    float acc[8][4];
#pragma unroll
    for (int i = 0; i < 8; i++)
#pragma unroll
        for (int j = 0; j < 4; j++) acc[i][j] = 0.f;

    for (int ii = 0; ii < RANK; ii++) {
        int row = sidx[ii];
        const float* Wr = W + row * LDW;
        float4 va0 = *(const float4*)&Wr[i0];
        float4 va1 = *(const float4*)&Wr[i0 + 4];
        float4 vb  = *(const float4*)&Wr[j0];
        float va[8] = {va0.x, va0.y, va0.z, va0.w, va1.x, va1.y, va1.z, va1.w};
        float vbv[4] = {vb.x, vb.y, vb.z, vb.w};
#pragma unroll
        for (int i = 0; i < 8; i++)
#pragma unroll
            for (int j = 0; j < 4; j++) acc[i][j] += va[i] * vbv[j];
    }
    float* Pp = &g_P[m][0][0];
#pragma unroll
    for (int i = 0; i < 8; i++) {
        float4 v = {acc[i][0], acc[i][1], acc[i][2], acc[i][3]};
        *(float4*)&Pp[(i0 + i) * MATN + j0] = v;
    }
}

// ---------------------------------------------------------------------------
// Kernel 3: Y = X · P  (grid: NM x 32 row-blocks of 64 rows, 256 threads)
// ---------------------------------------------------------------------------
#define LDX 129
#define REC_SMEM ((64 * LDX + MATN * MATN) * 4)

__global__ __launch_bounds__(256) void recon_kernel(const float* __restrict__ X,
                                                    float* __restrict__ out) {
    extern __shared__ float sm[];
    float* Xs = sm;              // 64 x 129
    float* Ps = sm + 64 * LDX;   // 128 x 128
    const int m = blockIdx.x, rb = blockIdx.y;
    const int t = threadIdx.x;

    const float* Xm = X + ((size_t)m * SLEN + (size_t)rb * 64) * MATN;
    for (int idx = t; idx < 64 * MATN; idx += 256) {
        int rI = idx >> 7, c = idx & 127;
        Xs[rI * LDX + c] = Xm[idx];
    }
    const float4* Pg = (const float4*)&g_P[m][0][0];
    float4* Pd = (float4*)Ps;
    for (int idx = t; idx < MATN * MATN / 4; idx += 256) Pd[idx] = Pg[idx];
    __syncthreads();

    const int r0 = (t >> 4) * 4, c0 = (t & 15) * 8;
    float acc[4][8];
#pragma unroll
    for (int i = 0; i < 4; i++)
#pragma unroll
        for (int j = 0; j < 8; j++) acc[i][j] = 0.f;

    for (int k = 0; k < MATN; k++) {
        float xv[4];
#pragma unroll
        for (int i = 0; i < 4; i++) xv[i] = Xs[(r0 + i) * LDX + k];
        float4 p0 = *(const float4*)&Ps[k * MATN + c0];
        float4 p1 = *(const float4*)&Ps[k * MATN + c0 + 4];
        float pv[8] = {p0.x, p0.y, p0.z, p0.w, p1.x, p1.y, p1.z, p1.w};
#pragma unroll
        for (int i = 0; i < 4; i++)
#pragma unroll
            for (int j = 0; j < 8; j++) acc[i][j] += xv[i] * pv[j];
    }

    float* Om = out + ((size_t)m * SLEN + (size_t)rb * 64) * MATN;
#pragma unroll
    for (int i = 0; i < 4; i++) {
        float4 v0 = {acc[i][0], acc[i][1], acc[i][2], acc[i][3]};
        float4 v1 = {acc[i][4], acc[i][5], acc[i][6], acc[i][7]};
        *(float4*)&Om[(r0 + i) * MATN + c0] = v0;
        *(float4*)&Om[(r0 + i) * MATN + c0 + 4] = v1;
    }
}

// ---------------------------------------------------------------------------
extern "C" void kernel_launch(void* const* d_in, const int* in_sizes, int n_in,
                              void* d_out, int out_size) {
    const float* X = (const float*)d_in[0];   // kv_cache fp32 (4,16,2048,128)
    float* out = (float*)d_out;               // fp32, same shape

    cudaFuncSetAttribute(jacobi_kernel, cudaFuncAttributeMaxDynamicSharedMemorySize, JAC_SMEM);
    cudaFuncSetAttribute(recon_kernel,  cudaFuncAttributeMaxDynamicSharedMemorySize, REC_SMEM);

    gram_kernel<<<dim3(NM, NPART), 256>>>(X);
    jacobi_kernel<<<NM, 512, JAC_SMEM>>>();
    recon_kernel<<<dim3(NM, 32), 256, REC_SMEM>>>(X, out);
}

// round 4
// speedup vs baseline: 2.4463x; 1.3888x over previous
#include <cuda_runtime.h>
#include <math.h>

#define NM     64      // number of matrices (B*H)
#define MATN   128     // matrix dim (D)
#define SLEN   2048    // sequence length
#define RANK   64
#define SWEEPS 7
#define ROUNDS 127     // MATN - 1
#define LDA    144     // A stride: 144 % 32 == 16 -> conflict-free (2 rows x 16 cols tiles)
#define LDW    132     // W stride: conflict-free float4 under (p + 2s) mapping
#define NPART  4       // gram split-K parts

// Scratch (device globals; no allocations allowed)
__device__ float g_G4[NPART][NM][MATN][MATN];  // partial Gram matrices (16 MB)
__device__ float g_P[NM][MATN][MATN];          // projectors (4 MB)

typedef unsigned long long u64t;
__device__ __forceinline__ u64t pack2(float lo, float hi) {
    u64t r; asm("mov.b64 %0,{%1,%2};" : "=l"(r) : "f"(lo), "f"(hi)); return r;
}
__device__ __forceinline__ u64t mul2(u64t a, u64t b) {
    u64t r; asm("mul.rn.f32x2 %0,%1,%2;" : "=l"(r) : "l"(a), "l"(b)); return r;
}
__device__ __forceinline__ u64t fma2(u64t a, u64t b, u64t c) {
    u64t r; asm("fma.rn.f32x2 %0,%1,%2,%3;" : "=l"(r) : "l"(a), "l"(b), "l"(c)); return r;
}

// Chess-tournament pairing: round rr in [0,127), pair index i in [0,64)
__device__ __forceinline__ void pair_pq(int i, int rr, int& p, int& q) {
    if (i == 0) { p = 0; }
    else { int x = i - 1 + rr; if (x >= 127) x -= 127; p = 1 + x; }
    int y = 126 - i + rr; if (y >= 127) y -= 127; q = 1 + y;
}

// ---------------------------------------------------------------------------
// Kernel 1: partial Gram  G_part = X_partᵀ X_part   (grid: NM x NPART, 256 thr)
// ---------------------------------------------------------------------------
__global__ __launch_bounds__(256) void gram_kernel(const float* __restrict__ X) {
    __shared__ float Xs[64][MATN];
    const int m = blockIdx.x, part = blockIdx.y;
    const int t = threadIdx.x;
    const int a0 = (t >> 4) * 8, b0 = (t & 15) * 8;
    float acc[8][8];
#pragma unroll
    for (int i = 0; i < 8; i++)
#pragma unroll
        for (int j = 0; j < 8; j++) acc[i][j] = 0.f;

    const float* Xm = X + ((size_t)m * SLEN + (size_t)part * 512) * MATN;
    for (int ch = 0; ch < 8; ch++) {
        const float4* src = (const float4*)(Xm + (size_t)ch * 64 * MATN);
        float4* dst = (float4*)&Xs[0][0];
#pragma unroll
        for (int j = 0; j < 8; j++) dst[t + 256 * j] = src[t + 256 * j];
        __syncthreads();
#pragma unroll 4
        for (int s = 0; s < 64; s++) {
            float4 a40 = *(const float4*)&Xs[s][a0];
            float4 a41 = *(const float4*)&Xs[s][a0 + 4];
            float4 b40 = *(const float4*)&Xs[s][b0];
            float4 b41 = *(const float4*)&Xs[s][b0 + 4];
            float av[8] = {a40.x, a40.y, a40.z, a40.w, a41.x, a41.y, a41.z, a41.w};
            float bv[8] = {b40.x, b40.y, b40.z, b40.w, b41.x, b41.y, b41.z, b41.w};
#pragma unroll
            for (int i = 0; i < 8; i++)
#pragma unroll
                for (int j = 0; j < 8; j++) acc[i][j] += av[i] * bv[j];
        }
        __syncthreads();
    }
    float* Gp = &g_G4[part][m][0][0];
#pragma unroll
    for (int i = 0; i < 8; i++) {
        float4 v0 = {acc[i][0], acc[i][1], acc[i][2], acc[i][3]};
        float4 v1 = {acc[i][4], acc[i][5], acc[i][6], acc[i][7]};
        *(float4*)&Gp[(a0 + i) * MATN + b0] = v0;
        *(float4*)&Gp[(a0 + i) * MATN + b0 + 4] = v1;
    }
}

// ---------------------------------------------------------------------------
// Kernel 2: Jacobi eigensolver per matrix + projector build
// grid: NM, 1024 threads, dynamic smem layout:
//   rot[64] float4 | A[128*144] | W[128*132] (W = Vᵀ) | ev[128] | sidx[64]
// ---------------------------------------------------------------------------
#define JAC_SMEM ((64 * 4 + MATN * LDA + MATN * LDW + MATN + 64) * 4)

__global__ __launch_bounds__(1024) void jacobi_kernel() {
    extern __shared__ float sm[];
    float4* rot = (float4*)sm;                 // 64 float4 (c, s, p, q)
    float*  A   = sm + 64 * 4;                 // 128 x 144
    float*  W   = A + MATN * LDA;              // 128 x 132 (rows = eigvecs)
    float*  ev  = W + MATN * LDW;              // 128
    int*    sidx = (int*)(ev + MATN);          // 64

    const int m = blockIdx.x, t = threadIdx.x;

    // Load A = sum of 4 Gram partials, W = I
    for (int idx = t; idx < MATN * MATN; idx += 1024) {
        int i = idx >> 7, j = idx & 127;
        A[i * LDA + j] = g_G4[0][m][i][j] + g_G4[1][m][i][j]
                       + g_G4[2][m][i][j] + g_G4[3][m][i][j];
        W[i * LDW + j] = (i == j) ? 1.f : 0.f;
    }
    __syncthreads();

    const int pa  = t >> 4;   // this thread's fixed pair index (0..63)
    const int sub = t & 15;   // sub-slot (0..15)

    for (int r = 0; r < SWEEPS * ROUNDS; r++) {
        const int rr = r - (r / ROUNDS) * ROUNDS;   // r % 127

        // Phase 0: rotation angles + pair LUT for the 64 disjoint pairs
        if (t < 64) {
            int p, q; pair_pq(t, rr, p, q);
            float app = A[p * LDA + p], aqq = A[q * LDA + q], apq = A[p * LDA + q];
            float c = 1.f, s = 0.f;
            float scl = fabsf(app) + fabsf(aqq);
            if (fabsf(apq) > 1e-12f * scl + 1e-38f) {
                float tau = (aqq - app) / (2.f * apq);
                float tt = 1.f / (fabsf(tau) + sqrtf(1.f + tau * tau));
                tt = (tau < 0.f) ? -tt : tt;
                c = rsqrtf(1.f + tt * tt);
                s = tt * c;
            }
            rot[t] = make_float4(c, s, __int_as_float(p), __int_as_float(q));
        }
        __syncthreads();

        float4 ra = rot[pa];
        const float ca = ra.x, sa = ra.y;
        const int p_a = __float_as_int(ra.z), q_a = __float_as_int(ra.w);
        float* Arp = A + p_a * LDA;
        float* Arq = A + q_a * LDA;

        // Phase 1a: fused 2x2 closure-block update A' = JᵀAJ
        // Each thread owns rows {p_a,q_a} x 4 column-pairs (bp = sub + 16k).
        // At fixed k a warp touches 2 row-pairs x 16 consecutive cols;
        // LDA=144 (≡16 mod 32) makes that conflict-free.
#pragma unroll
        for (int k = 0; k < 4; k++) {
            int bp = sub + (k << 4);
            float4 rb = rot[bp];
            float cb = rb.x, sb = rb.y;
            int p_b = __float_as_int(rb.z), q_b = __float_as_int(rb.w);
            float m00 = Arp[p_b], m01 = Arp[q_b];
            float m10 = Arq[p_b], m11 = Arq[q_b];
            float r00 = ca * m00 - sa * m10, r01 = ca * m01 - sa * m11;
            float r10 = sa * m00 + ca * m10, r11 = sa * m01 + ca * m11;
            Arp[p_b] = cb * r00 - sb * r01;
            Arp[q_b] = sb * r00 + cb * r01;
            Arq[p_b] = cb * r10 - sb * r11;
            Arq[q_b] = sb * r10 + cb * r11;
        }

        // Phase 1b: W = Vᵀ row rotation, packed f32x2 (8 cols per thread)
        {
            ulonglong2* Wp = (ulonglong2*)(W + p_a * LDW + (sub << 3));
            ulonglong2* Wq = (ulonglong2*)(W + q_a * LDW + (sub << 3));
            const u64t ca2  = pack2(ca, ca);
            const u64t sa2  = pack2(sa, sa);
            const u64t nsa2 = pack2(-sa, -sa);
#pragma unroll
            for (int i = 0; i < 2; i++) {
                ulonglong2 x = Wp[i], y = Wq[i];
                ulonglong2 nx, ny;
                nx.x = fma2(ca2, x.x, mul2(nsa2, y.x));
                nx.y = fma2(ca2, x.y, mul2(nsa2, y.y));
                ny.x = fma2(sa2, x.x, mul2(ca2, y.x));
                ny.y = fma2(sa2, x.y, mul2(ca2, y.y));
                Wp[i] = nx; Wq[i] = ny;
            }
        }
        __syncthreads();
    }

    // Eigenvalues + top-RANK selection (tie-break by index -> deterministic)
    if (t < MATN) ev[t] = A[t * LDA + t];
    __syncthreads();
    if (t < MATN) {
        float e = ev[t]; int rk = 0;
        for (int j = 0; j < MATN; j++) {
            float o = ev[j];
            if (o > e || (o == e && j < t)) rk++;
        }
        if (rk < RANK) sidx[rk] = t;
    }
    __syncthreads();

    // P = V_sel V_selᵀ = Σ_r W[r,:]ᵀ W[r,:] over the 64 selected rows of W
    const int i0 = (t >> 5) * 4, j0 = (t & 31) * 4;
    float acc[4][4];
#pragma unroll
    for (int i = 0; i < 4; i++)
#pragma unroll
        for (int j = 0; j < 4; j++) acc[i][j] = 0.f;

    for (int ii = 0; ii < RANK; ii++) {
        int row = sidx[ii];
        const float* Wr = W + row * LDW;
        float4 va4 = *(const float4*)&Wr[i0];
        float4 vb4 = *(const float4*)&Wr[j0];
        float va[4] = {va4.x, va4.y, va4.z, va4.w};
        float vb[4] = {vb4.x, vb4.y, vb4.z, vb4.w};
#pragma unroll
        for (int i = 0; i < 4; i++)
#pragma unroll
            for (int j = 0; j < 4; j++) acc[i][j] += va[i] * vb[j];
    }
    float* Pp = &g_P[m][0][0];
#pragma unroll
    for (int i = 0; i < 4; i++) {
        float4 v = {acc[i][0], acc[i][1], acc[i][2], acc[i][3]};
        *(float4*)&Pp[(i0 + i) * MATN + j0] = v;
    }
}

// ---------------------------------------------------------------------------
// Kernel 3: Y = X · P  (grid: NM x 32 row-blocks of 64 rows, 256 threads)
// ---------------------------------------------------------------------------
#define LDX 129
#define REC_SMEM ((64 * LDX + MATN * MATN) * 4)

__global__ __launch_bounds__(256) void recon_kernel(const float* __restrict__ X,
                                                    float* __restrict__ out) {
    extern __shared__ float sm[];
    float* Xs = sm;              // 64 x 129
    float* Ps = sm + 64 * LDX;   // 128 x 128
    const int m = blockIdx.x, rb = blockIdx.y;
    const int t = threadIdx.x;

    const float* Xm = X + ((size_t)m * SLEN + (size_t)rb * 64) * MATN;
    for (int idx = t; idx < 64 * MATN; idx += 256) {
        int rI = idx >> 7, c = idx & 127;
        Xs[rI * LDX + c] = Xm[idx];
    }
    const float4* Pg = (const float4*)&g_P[m][0][0];
    float4* Pd = (float4*)Ps;
    for (int idx = t; idx < MATN * MATN / 4; idx += 256) Pd[idx] = Pg[idx];
    __syncthreads();

    const int r0 = (t >> 4) * 4, c0 = (t & 15) * 8;
    float acc[4][8];
#pragma unroll
    for (int i = 0; i < 4; i++)
#pragma unroll
        for (int j = 0; j < 8; j++) acc[i][j] = 0.f;

    for (int k = 0; k < MATN; k++) {
        float xv[4];
#pragma unroll
        for (int i = 0; i < 4; i++) xv[i] = Xs[(r0 + i) * LDX + k];
        float4 p0 = *(const float4*)&Ps[k * MATN + c0];
        float4 p1 = *(const float4*)&Ps[k * MATN + c0 + 4];
        float pv[8] = {p0.x, p0.y, p0.z, p0.w, p1.x, p1.y, p1.z, p1.w};
#pragma unroll
        for (int i = 0; i < 4; i++)
#pragma unroll
            for (int j = 0; j < 8; j++) acc[i][j] += xv[i] * pv[j];
    }

    float* Om = out + ((size_t)m * SLEN + (size_t)rb * 64) * MATN;
#pragma unroll
    for (int i = 0; i < 4; i++) {
        float4 v0 = {acc[i][0], acc[i][1], acc[i][2], acc[i][3]};
        float4 v1 = {acc[i][4], acc[i][5], acc[i][6], acc[i][7]};
        *(float4*)&Om[(r0 + i) * MATN + c0] = v0;
        *(float4*)&Om[(r0 + i) * MATN + c0 + 4] = v1;
    }
}

// ---------------------------------------------------------------------------
extern "C" void kernel_launch(void* const* d_in, const int* in_sizes, int n_in,
                              void* d_out, int out_size) {
    const float* X = (const float*)d_in[0];   // kv_cache fp32 (4,16,2048,128)
    float* out = (float*)d_out;               // fp32, same shape

    cudaFuncSetAttribute(jacobi_kernel, cudaFuncAttributeMaxDynamicSharedMemorySize, JAC_SMEM);
    cudaFuncSetAttribute(recon_kernel,  cudaFuncAttributeMaxDynamicSharedMemorySize, REC_SMEM);

    gram_kernel<<<dim3(NM, NPART), 256>>>(X);
    jacobi_kernel<<<NM, 1024, JAC_SMEM>>>();
    recon_kernel<<<dim3(NM, 32), 256, REC_SMEM>>>(X, out);
}

// round 5
// speedup vs baseline: 2.4477x; 1.0006x over previous
#include <cuda_runtime.h>
#include <math.h>

#define NM     64      // number of matrices (B*H)
#define MATN   128     // matrix dim (D)
#define SLEN   2048    // sequence length
#define RANK   64
#define SWEEPS 7
#define ROUNDS 127     // MATN - 1
#define LDA    144     // A stride: 144 % 32 == 16 -> conflict-free (2 rows x 16 cols tiles)
#define LDW    132     // W stride: conflict-free float4 under (p + 2s) mapping
#define NPART  4       // gram split-K parts

// Scratch (device globals; no allocations allowed)
__device__ float g_G4[NPART][NM][MATN][MATN];  // partial Gram matrices (16 MB)
__device__ float g_P[NM][MATN][MATN];          // projectors (4 MB)

typedef unsigned long long u64t;
__device__ __forceinline__ u64t pack2(float lo, float hi) {
    u64t r; asm("mov.b64 %0,{%1,%2};" : "=l"(r) : "f"(lo), "f"(hi)); return r;
}
__device__ __forceinline__ u64t mul2(u64t a, u64t b) {
    u64t r; asm("mul.rn.f32x2 %0,%1,%2;" : "=l"(r) : "l"(a), "l"(b)); return r;
}
__device__ __forceinline__ u64t fma2(u64t a, u64t b, u64t c) {
    u64t r; asm("fma.rn.f32x2 %0,%1,%2,%3;" : "=l"(r) : "l"(a), "l"(b), "l"(c)); return r;
}

// Chess-tournament pairing: round rr in [0,127), pair index i in [0,64)
__device__ __forceinline__ void pair_pq(int i, int rr, int& p, int& q) {
    if (i == 0) { p = 0; }
    else { int x = i - 1 + rr; if (x >= 127) x -= 127; p = 1 + x; }
    int y = 126 - i + rr; if (y >= 127) y -= 127; q = 1 + y;
}

// ---------------------------------------------------------------------------
// Kernel 1: partial Gram  G_part = X_partᵀ X_part   (grid: NM x NPART, 256 thr)
// ---------------------------------------------------------------------------
__global__ __launch_bounds__(256) void gram_kernel(const float* __restrict__ X) {
    __shared__ float Xs[64][MATN];
    const int m = blockIdx.x, part = blockIdx.y;
    const int t = threadIdx.x;
    const int a0 = (t >> 4) * 8, b0 = (t & 15) * 8;
    float acc[8][8];
#pragma unroll
    for (int i = 0; i < 8; i++)
#pragma unroll
        for (int j = 0; j < 8; j++) acc[i][j] = 0.f;

    const float* Xm = X + ((size_t)m * SLEN + (size_t)part * 512) * MATN;
    for (int ch = 0; ch < 8; ch++) {
        const float4* src = (const float4*)(Xm + (size_t)ch * 64 * MATN);
        float4* dst = (float4*)&Xs[0][0];
#pragma unroll
        for (int j = 0; j < 8; j++) dst[t + 256 * j] = src[t + 256 * j];
        __syncthreads();
#pragma unroll 4
        for (int s = 0; s < 64; s++) {
            float4 a40 = *(const float4*)&Xs[s][a0];
            float4 a41 = *(const float4*)&Xs[s][a0 + 4];
            float4 b40 = *(const float4*)&Xs[s][b0];
            float4 b41 = *(const float4*)&Xs[s][b0 + 4];
            float av[8] = {a40.x, a40.y, a40.z, a40.w, a41.x, a41.y, a41.z, a41.w};
            float bv[8] = {b40.x, b40.y, b40.z, b40.w, b41.x, b41.y, b41.z, b41.w};
#pragma unroll
            for (int i = 0; i < 8; i++)
#pragma unroll
                for (int j = 0; j < 8; j++) acc[i][j] += av[i] * bv[j];
        }
        __syncthreads();
    }
    float* Gp = &g_G4[part][m][0][0];
#pragma unroll
    for (int i = 0; i < 8; i++) {
        float4 v0 = {acc[i][0], acc[i][1], acc[i][2], acc[i][3]};
        float4 v1 = {acc[i][4], acc[i][5], acc[i][6], acc[i][7]};
        *(float4*)&Gp[(a0 + i) * MATN + b0] = v0;
        *(float4*)&Gp[(a0 + i) * MATN + b0 + 4] = v1;
    }
}

// ---------------------------------------------------------------------------
// Kernel 2: Jacobi eigensolver per matrix + projector build
// grid: NM, 1024 threads, dynamic smem layout:
//   rot[64] float4 | A[128*144] | W[128*132] (W = Vᵀ) | ev[128] | sidx[64]
// ---------------------------------------------------------------------------
#define JAC_SMEM ((64 * 4 + MATN * LDA + MATN * LDW + MATN + 64) * 4)

__global__ __launch_bounds__(1024) void jacobi_kernel() {
    extern __shared__ float sm[];
    float4* rot = (float4*)sm;                 // 64 float4 (c, s, p, q)
    float*  A   = sm + 64 * 4;                 // 128 x 144
    float*  W   = A + MATN * LDA;              // 128 x 132 (rows = eigvecs)
    float*  ev  = W + MATN * LDW;              // 128
    int*    sidx = (int*)(ev + MATN);          // 64

    const int m = blockIdx.x, t = threadIdx.x;

    // Load A = sum of 4 Gram partials, W = I
    for (int idx = t; idx < MATN * MATN; idx += 1024) {
        int i = idx >> 7, j = idx & 127;
        A[i * LDA + j] = g_G4[0][m][i][j] + g_G4[1][m][i][j]
                       + g_G4[2][m][i][j] + g_G4[3][m][i][j];
        W[i * LDW + j] = (i == j) ? 1.f : 0.f;
    }
    __syncthreads();

    const int pa  = t >> 4;   // this thread's fixed pair index (0..63)
    const int sub = t & 15;   // sub-slot (0..15)

    for (int r = 0; r < SWEEPS * ROUNDS; r++) {
        const int rr = r - (r / ROUNDS) * ROUNDS;   // r % 127

        // Phase 0: rotation angles + pair LUT for the 64 disjoint pairs
        if (t < 64) {
            int p, q; pair_pq(t, rr, p, q);
            float app = A[p * LDA + p], aqq = A[q * LDA + q], apq = A[p * LDA + q];
            float c = 1.f, s = 0.f;
            float scl = fabsf(app) + fabsf(aqq);
            if (fabsf(apq) > 1e-12f * scl + 1e-38f) {
                float tau = (aqq - app) / (2.f * apq);
                float tt = 1.f / (fabsf(tau) + sqrtf(1.f + tau * tau));
                tt = (tau < 0.f) ? -tt : tt;
                c = rsqrtf(1.f + tt * tt);
                s = tt * c;
            }
            rot[t] = make_float4(c, s, __int_as_float(p), __int_as_float(q));
        }
        __syncthreads();

        float4 ra = rot[pa];
        const float ca = ra.x, sa = ra.y;
        const int p_a = __float_as_int(ra.z), q_a = __float_as_int(ra.w);
        float* Arp = A + p_a * LDA;
        float* Arq = A + q_a * LDA;

        // Phase 1a: fused 2x2 closure-block update A' = JᵀAJ
        // Each thread owns rows {p_a,q_a} x 4 column-pairs (bp = sub + 16k).
        // At fixed k a warp touches 2 row-pairs x 16 consecutive cols;
        // LDA=144 (≡16 mod 32) makes that conflict-free.
#pragma unroll
        for (int k = 0; k < 4; k++) {
            int bp = sub + (k << 4);
            float4 rb = rot[bp];
            float cb = rb.x, sb = rb.y;
            int p_b = __float_as_int(rb.z), q_b = __float_as_int(rb.w);
            float m00 = Arp[p_b], m01 = Arp[q_b];
            float m10 = Arq[p_b], m11 = Arq[q_b];
            float r00 = ca * m00 - sa * m10, r01 = ca * m01 - sa * m11;
            float r10 = sa * m00 + ca * m10, r11 = sa * m01 + ca * m11;
            Arp[p_b] = cb * r00 - sb * r01;
            Arp[q_b] = sb * r00 + cb * r01;
            Arq[p_b] = cb * r10 - sb * r11;
            Arq[q_b] = sb * r10 + cb * r11;
        }

        // Phase 1b: W = Vᵀ row rotation, packed f32x2 (8 cols per thread)
        {
            ulonglong2* Wp = (ulonglong2*)(W + p_a * LDW + (sub << 3));
            ulonglong2* Wq = (ulonglong2*)(W + q_a * LDW + (sub << 3));
            const u64t ca2  = pack2(ca, ca);
            const u64t sa2  = pack2(sa, sa);
            const u64t nsa2 = pack2(-sa, -sa);
#pragma unroll
            for (int i = 0; i < 2; i++) {
                ulonglong2 x = Wp[i], y = Wq[i];
                ulonglong2 nx, ny;
                nx.x = fma2(ca2, x.x, mul2(nsa2, y.x));
                nx.y = fma2(ca2, x.y, mul2(nsa2, y.y));
                ny.x = fma2(sa2, x.x, mul2(ca2, y.x));
                ny.y = fma2(sa2, x.y, mul2(ca2, y.y));
                Wp[i] = nx; Wq[i] = ny;
            }
        }
        __syncthreads();
    }

    // Eigenvalues + top-RANK selection (tie-break by index -> deterministic)
    if (t < MATN) ev[t] = A[t * LDA + t];
    __syncthreads();
    if (t < MATN) {
        float e = ev[t]; int rk = 0;
        for (int j = 0; j < MATN; j++) {
            float o = ev[j];
            if (o > e || (o == e && j < t)) rk++;
        }
        if (rk < RANK) sidx[rk] = t;
    }
    __syncthreads();

    // P = V_sel V_selᵀ = Σ_r W[r,:]ᵀ W[r,:] over the 64 selected rows of W
    const int i0 = (t >> 5) * 4, j0 = (t & 31) * 4;
    float acc[4][4];
#pragma unroll
    for (int i = 0; i < 4; i++)
#pragma unroll
        for (int j = 0; j < 4; j++) acc[i][j] = 0.f;

    for (int ii = 0; ii < RANK; ii++) {
        int row = sidx[ii];
        const float* Wr = W + row * LDW;
        float4 va4 = *(const float4*)&Wr[i0];
        float4 vb4 = *(const float4*)&Wr[j0];
        float va[4] = {va4.x, va4.y, va4.z, va4.w};
        float vb[4] = {vb4.x, vb4.y, vb4.z, vb4.w};
#pragma unroll
        for (int i = 0; i < 4; i++)
#pragma unroll
            for (int j = 0; j < 4; j++) acc[i][j] += va[i] * vb[j];
    }
    float* Pp = &g_P[m][0][0];
#pragma unroll
    for (int i = 0; i < 4; i++) {
        float4 v = {acc[i][0], acc[i][1], acc[i][2], acc[i][3]};
        *(float4*)&Pp[(i0 + i) * MATN + j0] = v;
    }
}

// ---------------------------------------------------------------------------
// Kernel 3: Y = X · P  (grid: NM x 32 row-blocks of 64 rows, 256 threads)
// ---------------------------------------------------------------------------
#define LDX 129
#define REC_SMEM ((64 * LDX + MATN * MATN) * 4)

__global__ __launch_bounds__(256) void recon_kernel(const float* __restrict__ X,
                                                    float* __restrict__ out) {
    extern __shared__ float sm[];
    float* Xs = sm;              // 64 x 129
    float* Ps = sm + 64 * LDX;   // 128 x 128
    const int m = blockIdx.x, rb = blockIdx.y;
    const int t = threadIdx.x;

    const float* Xm = X + ((size_t)m * SLEN + (size_t)rb * 64) * MATN;
    for (int idx = t; idx < 64 * MATN; idx += 256) {
        int rI = idx >> 7, c = idx & 127;
        Xs[rI * LDX + c] = Xm[idx];
    }
    const float4* Pg = (const float4*)&g_P[m][0][0];
    float4* Pd = (float4*)Ps;
    for (int idx = t; idx < MATN * MATN / 4; idx += 256) Pd[idx] = Pg[idx];
    __syncthreads();

    const int r0 = (t >> 4) * 4, c0 = (t & 15) * 8;
    float acc[4][8];
#pragma unroll
    for (int i = 0; i < 4; i++)
#pragma unroll
        for (int j = 0; j < 8; j++) acc[i][j] = 0.f;

    for (int k = 0; k < MATN; k++) {
        float xv[4];
#pragma unroll
        for (int i = 0; i < 4; i++) xv[i] = Xs[(r0 + i) * LDX + k];
        float4 p0 = *(const float4*)&Ps[k * MATN + c0];
        float4 p1 = *(const float4*)&Ps[k * MATN + c0 + 4];
        float pv[8] = {p0.x, p0.y, p0.z, p0.w, p1.x, p1.y, p1.z, p1.w};
#pragma unroll
        for (int i = 0; i < 4; i++)
#pragma unroll
            for (int j = 0; j < 8; j++) acc[i][j] += xv[i] * pv[j];
    }

    float* Om = out + ((size_t)m * SLEN + (size_t)rb * 64) * MATN;
#pragma unroll
    for (int i = 0; i < 4; i++) {
        float4 v0 = {acc[i][0], acc[i][1], acc[i][2], acc[i][3]};
        float4 v1 = {acc[i][4], acc[i][5], acc[i][6], acc[i][7]};
        *(float4*)&Om[(r0 + i) * MATN + c0] = v0;
        *(float4*)&Om[(r0 + i) * MATN + c0 + 4] = v1;
    }
}

// ---------------------------------------------------------------------------
extern "C" void kernel_launch(void* const* d_in, const int* in_sizes, int n_in,
                              void* d_out, int out_size) {
    const float* X = (const float*)d_in[0];   // kv_cache fp32 (4,16,2048,128)
    float* out = (float*)d_out;               // fp32, same shape

    cudaFuncSetAttribute(jacobi_kernel, cudaFuncAttributeMaxDynamicSharedMemorySize, JAC_SMEM);
    cudaFuncSetAttribute(recon_kernel,  cudaFuncAttributeMaxDynamicSharedMemorySize, REC_SMEM);

    gram_kernel<<<dim3(NM, NPART), 256>>>(X);
    jacobi_kernel<<<NM, 1024, JAC_SMEM>>>();
    recon_kernel<<<dim3(NM, 32), 256, REC_SMEM>>>(X, out);
}

// round 6
// speedup vs baseline: 2.4481x; 1.0002x over previous
#include <cuda_runtime.h>
#include <math.h>

#define NM     64      // number of matrices (B*H)
#define MATN   128     // matrix dim (D)
#define SLEN   2048    // sequence length
#define RANK   64
#define SWEEPS 7
#define ROUNDS 127     // MATN - 1
#define LDA    144     // A stride: 144 % 32 == 16 -> conflict-free (2 rows x 16 cols tiles)
#define LDW    132     // W stride: conflict-free float4 under (p + 2s) mapping
#define NPART  4       // gram split-K parts

// Scratch (device globals; no allocations allowed)
__device__ float g_G4[NPART][NM][MATN][MATN];  // partial Gram matrices (16 MB)
__device__ float g_P[NM][MATN][MATN];          // projectors (4 MB)

typedef unsigned long long u64t;
__device__ __forceinline__ u64t pack2(float lo, float hi) {
    u64t r; asm("mov.b64 %0,{%1,%2};" : "=l"(r) : "f"(lo), "f"(hi)); return r;
}
__device__ __forceinline__ u64t mul2(u64t a, u64t b) {
    u64t r; asm("mul.rn.f32x2 %0,%1,%2;" : "=l"(r) : "l"(a), "l"(b)); return r;
}
__device__ __forceinline__ u64t fma2(u64t a, u64t b, u64t c) {
    u64t r; asm("fma.rn.f32x2 %0,%1,%2,%3;" : "=l"(r) : "l"(a), "l"(b), "l"(c)); return r;
}

// Chess-tournament pairing: round rr in [0,127), pair index i in [0,64)
__device__ __forceinline__ void pair_pq(int i, int rr, int& p, int& q) {
    if (i == 0) { p = 0; }
    else { int x = i - 1 + rr; if (x >= 127) x -= 127; p = 1 + x; }
    int y = 126 - i + rr; if (y >= 127) y -= 127; q = 1 + y;
}

// ---------------------------------------------------------------------------
// Kernel 1: partial Gram  G_part = X_partᵀ X_part   (grid: NM x NPART, 256 thr)
// ---------------------------------------------------------------------------
__global__ __launch_bounds__(256) void gram_kernel(const float* __restrict__ X) {
    __shared__ float Xs[64][MATN];
    const int m = blockIdx.x, part = blockIdx.y;
    const int t = threadIdx.x;
    const int a0 = (t >> 4) * 8, b0 = (t & 15) * 8;
    float acc[8][8];
#pragma unroll
    for (int i = 0; i < 8; i++)
#pragma unroll
        for (int j = 0; j < 8; j++) acc[i][j] = 0.f;

    const float* Xm = X + ((size_t)m * SLEN + (size_t)part * 512) * MATN;
    for (int ch = 0; ch < 8; ch++) {
        const float4* src = (const float4*)(Xm + (size_t)ch * 64 * MATN);
        float4* dst = (float4*)&Xs[0][0];
#pragma unroll
        for (int j = 0; j < 8; j++) dst[t + 256 * j] = src[t + 256 * j];
        __syncthreads();
#pragma unroll 4
        for (int s = 0; s < 64; s++) {
            float4 a40 = *(const float4*)&Xs[s][a0];
            float4 a41 = *(const float4*)&Xs[s][a0 + 4];
            float4 b40 = *(const float4*)&Xs[s][b0];
            float4 b41 = *(const float4*)&Xs[s][b0 + 4];
            float av[8] = {a40.x, a40.y, a40.z, a40.w, a41.x, a41.y, a41.z, a41.w};
            float bv[8] = {b40.x, b40.y, b40.z, b40.w, b41.x, b41.y, b41.z, b41.w};
#pragma unroll
            for (int i = 0; i < 8; i++)
#pragma unroll
                for (int j = 0; j < 8; j++) acc[i][j] += av[i] * bv[j];
        }
        __syncthreads();
    }
    float* Gp = &g_G4[part][m][0][0];
#pragma unroll
    for (int i = 0; i < 8; i++) {
        float4 v0 = {acc[i][0], acc[i][1], acc[i][2], acc[i][3]};
        float4 v1 = {acc[i][4], acc[i][5], acc[i][6], acc[i][7]};
        *(float4*)&Gp[(a0 + i) * MATN + b0] = v0;
        *(float4*)&Gp[(a0 + i) * MATN + b0 + 4] = v1;
    }
}

// ---------------------------------------------------------------------------
// Kernel 2: Jacobi eigensolver per matrix + projector build
// grid: NM, 1024 threads, dynamic smem layout:
//   rot[64] float4 | A[128*144] | W[128*132] (W = Vᵀ) | ev[128] | sidx[64]
// ---------------------------------------------------------------------------
#define JAC_SMEM ((64 * 4 + MATN * LDA + MATN * LDW + MATN + 64) * 4)

__global__ __launch_bounds__(1024) void jacobi_kernel() {
    extern __shared__ float sm[];
    float4* rot = (float4*)sm;                 // 64 float4 (c, s, p, q)
    float*  A   = sm + 64 * 4;                 // 128 x 144
    float*  W   = A + MATN * LDA;              // 128 x 132 (rows = eigvecs)
    float*  ev  = W + MATN * LDW;              // 128
    int*    sidx = (int*)(ev + MATN);          // 64

    const int m = blockIdx.x, t = threadIdx.x;

    // Load A = sum of 4 Gram partials, W = I
    for (int idx = t; idx < MATN * MATN; idx += 1024) {
        int i = idx >> 7, j = idx & 127;
        A[i * LDA + j] = g_G4[0][m][i][j] + g_G4[1][m][i][j]
                       + g_G4[2][m][i][j] + g_G4[3][m][i][j];
        W[i * LDW + j] = (i == j) ? 1.f : 0.f;
    }
    __syncthreads();

    const int pa  = t >> 4;   // this thread's fixed pair index (0..63)
    const int sub = t & 15;   // sub-slot (0..15)

    for (int r = 0; r < SWEEPS * ROUNDS; r++) {
        const int rr = r - (r / ROUNDS) * ROUNDS;   // r % 127

        // Phase 0: rotation angles + pair LUT for the 64 disjoint pairs
        if (t < 64) {
            int p, q; pair_pq(t, rr, p, q);
            float app = A[p * LDA + p], aqq = A[q * LDA + q], apq = A[p * LDA + q];
            float c = 1.f, s = 0.f;
            float scl = fabsf(app) + fabsf(aqq);
            if (fabsf(apq) > 1e-12f * scl + 1e-38f) {
                float tau = (aqq - app) / (2.f * apq);
                float tt = 1.f / (fabsf(tau) + sqrtf(1.f + tau * tau));
                tt = (tau < 0.f) ? -tt : tt;
                c = rsqrtf(1.f + tt * tt);
                s = tt * c;
            }
            rot[t] = make_float4(c, s, __int_as_float(p), __int_as_float(q));
        }
        __syncthreads();

        float4 ra = rot[pa];
        const float ca = ra.x, sa = ra.y;
        const int p_a = __float_as_int(ra.z), q_a = __float_as_int(ra.w);
        float* Arp = A + p_a * LDA;
        float* Arq = A + q_a * LDA;

        // Phase 1a: fused 2x2 closure-block update A' = JᵀAJ
        // Each thread owns rows {p_a,q_a} x 4 column-pairs (bp = sub + 16k).
        // At fixed k a warp touches 2 row-pairs x 16 consecutive cols;
        // LDA=144 (≡16 mod 32) makes that conflict-free.
#pragma unroll
        for (int k = 0; k < 4; k++) {
            int bp = sub + (k << 4);
            float4 rb = rot[bp];
            float cb = rb.x, sb = rb.y;
            int p_b = __float_as_int(rb.z), q_b = __float_as_int(rb.w);
            float m00 = Arp[p_b], m01 = Arp[q_b];
            float m10 = Arq[p_b], m11 = Arq[q_b];
            float r00 = ca * m00 - sa * m10, r01 = ca * m01 - sa * m11;
            float r10 = sa * m00 + ca * m10, r11 = sa * m01 + ca * m11;
            Arp[p_b] = cb * r00 - sb * r01;
            Arp[q_b] = sb * r00 + cb * r01;
            Arq[p_b] = cb * r10 - sb * r11;
            Arq[q_b] = sb * r10 + cb * r11;
        }

        // Phase 1b: W = Vᵀ row rotation, packed f32x2 (8 cols per thread)
        {
            ulonglong2* Wp = (ulonglong2*)(W + p_a * LDW + (sub << 3));
            ulonglong2* Wq = (ulonglong2*)(W + q_a * LDW + (sub << 3));
            const u64t ca2  = pack2(ca, ca);
            const u64t sa2  = pack2(sa, sa);
            const u64t nsa2 = pack2(-sa, -sa);
#pragma unroll
            for (int i = 0; i < 2; i++) {
                ulonglong2 x = Wp[i], y = Wq[i];
                ulonglong2 nx, ny;
                nx.x = fma2(ca2, x.x, mul2(nsa2, y.x));
                nx.y = fma2(ca2, x.y, mul2(nsa2, y.y));
                ny.x = fma2(sa2, x.x, mul2(ca2, y.x));
                ny.y = fma2(sa2, x.y, mul2(ca2, y.y));
                Wp[i] = nx; Wq[i] = ny;
            }
        }
        __syncthreads();
    }

    // Eigenvalues + top-RANK selection (tie-break by index -> deterministic)
    if (t < MATN) ev[t] = A[t * LDA + t];
    __syncthreads();
    if (t < MATN) {
        float e = ev[t]; int rk = 0;
        for (int j = 0; j < MATN; j++) {
            float o = ev[j];
            if (o > e || (o == e && j < t)) rk++;
        }
        if (rk < RANK) sidx[rk] = t;
    }
    __syncthreads();

    // P = V_sel V_selᵀ = Σ_r W[r,:]ᵀ W[r,:] over the 64 selected rows of W
    const int i0 = (t >> 5) * 4, j0 = (t & 31) * 4;
    float acc[4][4];
#pragma unroll
    for (int i = 0; i < 4; i++)
#pragma unroll
        for (int j = 0; j < 4; j++) acc[i][j] = 0.f;

    for (int ii = 0; ii < RANK; ii++) {
        int row = sidx[ii];
        const float* Wr = W + row * LDW;
        float4 va4 = *(const float4*)&Wr[i0];
        float4 vb4 = *(const float4*)&Wr[j0];
        float va[4] = {va4.x, va4.y, va4.z, va4.w};
        float vb[4] = {vb4.x, vb4.y, vb4.z, vb4.w};
#pragma unroll
        for (int i = 0; i < 4; i++)
#pragma unroll
            for (int j = 0; j < 4; j++) acc[i][j] += va[i] * vb[j];
    }
    float* Pp = &g_P[m][0][0];
#pragma unroll
    for (int i = 0; i < 4; i++) {
        float4 v = {acc[i][0], acc[i][1], acc[i][2], acc[i][3]};
        *(float4*)&Pp[(i0 + i) * MATN + j0] = v;
    }
}

// ---------------------------------------------------------------------------
// Kernel 3: Y = X · P  (grid: NM x 32 row-blocks of 64 rows, 256 threads)
// ---------------------------------------------------------------------------
#define LDX 129
#define REC_SMEM ((64 * LDX + MATN * MATN) * 4)

__global__ __launch_bounds__(256) void recon_kernel(const float* __restrict__ X,
                                                    float* __restrict__ out) {
    extern __shared__ float sm[];
    float* Xs = sm;              // 64 x 129
    float* Ps = sm + 64 * LDX;   // 128 x 128
    const int m = blockIdx.x, rb = blockIdx.y;
    const int t = threadIdx.x;

    const float* Xm = X + ((size_t)m * SLEN + (size_t)rb * 64) * MATN;
    for (int idx = t; idx < 64 * MATN; idx += 256) {
        int rI = idx >> 7, c = idx & 127;
        Xs[rI * LDX + c] = Xm[idx];
    }
    const float4* Pg = (const float4*)&g_P[m][0][0];
    float4* Pd = (float4*)Ps;
    for (int idx = t; idx < MATN * MATN / 4; idx += 256) Pd[idx] = Pg[idx];
    __syncthreads();

    const int r0 = (t >> 4) * 4, c0 = (t & 15) * 8;
    float acc[4][8];
#pragma unroll
    for (int i = 0; i < 4; i++)
#pragma unroll
        for (int j = 0; j < 8; j++) acc[i][j] = 0.f;

    for (int k = 0; k < MATN; k++) {
        float xv[4];
#pragma unroll
        for (int i = 0; i < 4; i++) xv[i] = Xs[(r0 + i) * LDX + k];
        float4 p0 = *(const float4*)&Ps[k * MATN + c0];
        float4 p1 = *(const float4*)&Ps[k * MATN + c0 + 4];
        float pv[8] = {p0.x, p0.y, p0.z, p0.w, p1.x, p1.y, p1.z, p1.w};
#pragma unroll
        for (int i = 0; i < 4; i++)
#pragma unroll
            for (int j = 0; j < 8; j++) acc[i][j] += xv[i] * pv[j];
    }

    float* Om = out + ((size_t)m * SLEN + (size_t)rb * 64) * MATN;
#pragma unroll
    for (int i = 0; i < 4; i++) {
        float4 v0 = {acc[i][0], acc[i][1], acc[i][2], acc[i][3]};
        float4 v1 = {acc[i][4], acc[i][5], acc[i][6], acc[i][7]};
        *(float4*)&Om[(r0 + i) * MATN + c0] = v0;
        *(float4*)&Om[(r0 + i) * MATN + c0 + 4] = v1;
    }
}

// ---------------------------------------------------------------------------
extern "C" void kernel_launch(void* const* d_in, const int* in_sizes, int n_in,
                              void* d_out, int out_size) {
    const float* X = (const float*)d_in[0];   // kv_cache fp32 (4,16,2048,128)
    float* out = (float*)d_out;               // fp32, same shape

    cudaFuncSetAttribute(jacobi_kernel, cudaFuncAttributeMaxDynamicSharedMemorySize, JAC_SMEM);
    cudaFuncSetAttribute(recon_kernel,  cudaFuncAttributeMaxDynamicSharedMemorySize, REC_SMEM);

    gram_kernel<<<dim3(NM, NPART), 256>>>(X);
    jacobi_kernel<<<NM, 1024, JAC_SMEM>>>();
    recon_kernel<<<dim3(NM, 32), 256, REC_SMEM>>>(X, out);
}

// round 8
// speedup vs baseline: 2.6070x; 1.0649x over previous
#include <cuda_runtime.h>
#include <math.h>

#define NM     64      // number of matrices (B*H)
#define MATN   128     // matrix dim (D)
#define SLEN   2048    // sequence length
#define RANK   64
#define SWEEPS 7
#define ROUNDS 127     // MATN - 1
#define TOTR   (SWEEPS * ROUNDS)
#define LDA    144     // A stride: 144 % 32 == 16 -> conflict-free (2 rows x 16 cols tiles)
#define LDW    132     // W stride: conflict-free float4 under (p + 2s) mapping
#define NPART  4       // gram split-K parts

// Scratch (device globals; no allocations allowed)
__device__ float g_G4[NPART][NM][MATN][MATN];  // partial Gram matrices (16 MB)
__device__ float g_P[NM][MATN][MATN];          // projectors (4 MB)

typedef unsigned long long u64t;
__device__ __forceinline__ u64t pack2(float lo, float hi) {
    u64t r; asm("mov.b64 %0,{%1,%2};" : "=l"(r) : "f"(lo), "f"(hi)); return r;
}
__device__ __forceinline__ u64t mul2(u64t a, u64t b) {
    u64t r; asm("mul.rn.f32x2 %0,%1,%2;" : "=l"(r) : "l"(a), "l"(b)); return r;
}
__device__ __forceinline__ u64t fma2(u64t a, u64t b, u64t c) {
    u64t r; asm("fma.rn.f32x2 %0,%1,%2,%3;" : "=l"(r) : "l"(a), "l"(b), "l"(c)); return r;
}

// Chess-tournament pairing: round rr in [0,127), pair index i in [0,64)
__device__ __forceinline__ void pair_pq(int i, int rr, int& p, int& q) {
    if (i == 0) { p = 0; }
    else { int x = i - 1 + rr; if (x >= 127) x -= 127; p = 1 + x; }
    int y = 126 - i + rr; if (y >= 127) y -= 127; q = 1 + y;
}

// ---------------------------------------------------------------------------
// Kernel 1: partial Gram  G_part = X_partᵀ X_part   (grid: NM x NPART, 256 thr)
// ---------------------------------------------------------------------------
__global__ __launch_bounds__(256) void gram_kernel(const float* __restrict__ X) {
    __shared__ float Xs[64][MATN];
    const int m = blockIdx.x, part = blockIdx.y;
    const int t = threadIdx.x;
    const int a0 = (t >> 4) * 8, b0 = (t & 15) * 8;
    float acc[8][8];
#pragma unroll
    for (int i = 0; i < 8; i++)
#pragma unroll
        for (int j = 0; j < 8; j++) acc[i][j] = 0.f;

    const float* Xm = X + ((size_t)m * SLEN + (size_t)part * 512) * MATN;
    for (int ch = 0; ch < 8; ch++) {
        const float4* src = (const float4*)(Xm + (size_t)ch * 64 * MATN);
        float4* dst = (float4*)&Xs[0][0];
#pragma unroll
        for (int j = 0; j < 8; j++) dst[t + 256 * j] = src[t + 256 * j];
        __syncthreads();
#pragma unroll 4
        for (int s = 0; s < 64; s++) {
            float4 a40 = *(const float4*)&Xs[s][a0];
            float4 a41 = *(const float4*)&Xs[s][a0 + 4];
            float4 b40 = *(const float4*)&Xs[s][b0];
            float4 b41 = *(const float4*)&Xs[s][b0 + 4];
            float av[8] = {a40.x, a40.y, a40.z, a40.w, a41.x, a41.y, a41.z, a41.w};
            float bv[8] = {b40.x, b40.y, b40.z, b40.w, b41.x, b41.y, b41.z, b41.w};
#pragma unroll
            for (int i = 0; i < 8; i++)
#pragma unroll
                for (int j = 0; j < 8; j++) acc[i][j] += av[i] * bv[j];
        }
        __syncthreads();
    }
    float* Gp = &g_G4[part][m][0][0];
#pragma unroll
    for (int i = 0; i < 8; i++) {
        float4 v0 = {acc[i][0], acc[i][1], acc[i][2], acc[i][3]};
        float4 v1 = {acc[i][4], acc[i][5], acc[i][6], acc[i][7]};
        *(float4*)&Gp[(a0 + i) * MATN + b0] = v0;
        *(float4*)&Gp[(a0 + i) * MATN + b0 + 4] = v1;
    }
}

// ---------------------------------------------------------------------------
// Kernel 2: Jacobi eigensolver per matrix + projector build
// grid: NM, 1024 threads, dynamic smem layout:
//   rot[2][64] float4 (double-buffered) | A[128*144] | W[128*132] | ev | sidx
// ---------------------------------------------------------------------------
#define JAC_SMEM ((128 * 4 + MATN * LDA + MATN * LDW + MATN + 64) * 4)

__global__ __launch_bounds__(1024) void jacobi_kernel() {
    extern __shared__ float sm[];
    float4* rotb = (float4*)sm;                // 2 x 64 float4 (c, s, p, q)
    float*  A   = sm + 128 * 4;                // 128 x 144
    float*  W   = A + MATN * LDA;              // 128 x 132 (rows = eigvecs)
    float*  ev  = W + MATN * LDW;              // 128
    int*    sidx = (int*)(ev + MATN);          // 64

    const int m = blockIdx.x, t = threadIdx.x;

    // Load A = sum of 4 Gram partials, W = I
    for (int idx = t; idx < MATN * MATN; idx += 1024) {
        int i = idx >> 7, j = idx & 127;
        A[i * LDA + j] = g_G4[0][m][i][j] + g_G4[1][m][i][j]
                       + g_G4[2][m][i][j] + g_G4[3][m][i][j];
        W[i * LDW + j] = (i == j) ? 1.f : 0.f;
    }
    __syncthreads();

    const int pa  = t >> 4;   // this thread's fixed pair index (0..63)
    const int sub = t & 15;   // sub-slot (0..15)

    // Prologue: rotations for round 0 into buffer 0
    if (t < 64) {
        int p, q; pair_pq(t, 0, p, q);
        float app = A[p * LDA + p], aqq = A[q * LDA + q], apq = A[p * LDA + q];
        float c = 1.f, s = 0.f;
        float scl = fabsf(app) + fabsf(aqq);
        if (fabsf(apq) > 1e-12f * scl + 1e-38f) {
            float tau = (aqq - app) / (2.f * apq);
            float tt = 1.f / (fabsf(tau) + sqrtf(1.f + tau * tau));
            tt = (tau < 0.f) ? -tt : tt;
            c = rsqrtf(1.f + tt * tt);
            s = tt * c;
        }
        rotb[t] = make_float4(c, s, __int_as_float(p), __int_as_float(q));
    }
    __syncthreads();

    for (int r = 0; r < TOTR; r++) {
        float4* rot = rotb + ((r & 1) << 6);

        float4 ra = rot[pa];
        const float ca = ra.x, sa = ra.y;
        const int p_a = __float_as_int(ra.z), q_a = __float_as_int(ra.w);
        float* Arp = A + p_a * LDA;
        float* Arq = A + q_a * LDA;

        // Phase 1a: fused 2x2 closure-block update A' = JᵀAJ
        // Each thread owns rows {p_a,q_a} x 4 column-pairs (bp = sub + 16k).
#pragma unroll
        for (int k = 0; k < 4; k++) {
            int bp = sub + (k << 4);
            float4 rb = rot[bp];
            float cb = rb.x, sb = rb.y;
            int p_b = __float_as_int(rb.z), q_b = __float_as_int(rb.w);
            float m00 = Arp[p_b], m01 = Arp[q_b];
            float m10 = Arq[p_b], m11 = Arq[q_b];
            float r00 = ca * m00 - sa * m10, r01 = ca * m01 - sa * m11;
            float r10 = sa * m00 + ca * m10, r11 = sa * m01 + ca * m11;
            Arp[p_b] = cb * r00 - sb * r01;
            Arp[q_b] = sb * r00 + cb * r01;
            Arq[p_b] = cb * r10 - sb * r11;
            Arq[q_b] = sb * r10 + cb * r11;
        }
        __syncthreads();

        // Phase 0 (for round r+1) overlapped with Phase 1b (round r).
        // Phase0 reads A (final after 1a above); 1b touches only W.
        if (t < 64 && r + 1 < TOTR) {
            int rr1 = r + 1; rr1 -= (rr1 / ROUNDS) * ROUNDS;  // (r+1) % 127
            int p, q; pair_pq(t, rr1, p, q);
            float app = A[p * LDA + p], aqq = A[q * LDA + q], apq = A[p * LDA + q];
            float c = 1.f, s = 0.f;
            float scl = fabsf(app) + fabsf(aqq);
            if (fabsf(apq) > 1e-12f * scl + 1e-38f) {
                float tau = (aqq - app) / (2.f * apq);
                float tt = 1.f / (fabsf(tau) + sqrtf(1.f + tau * tau));
                tt = (tau < 0.f) ? -tt : tt;
                c = rsqrtf(1.f + tt * tt);
                s = tt * c;
            }
            rotb[((~r & 1) << 6) + t] = make_float4(c, s, __int_as_float(p), __int_as_float(q));
        }

        // Phase 1b: W = Vᵀ row rotation, packed f32x2 (8 cols per thread)
        {
            ulonglong2* Wp = (ulonglong2*)(W + p_a * LDW + (sub << 3));
            ulonglong2* Wq = (ulonglong2*)(W + q_a * LDW + (sub << 3));
            const u64t ca2  = pack2(ca, ca);
            const u64t sa2  = pack2(sa, sa);
            const u64t nsa2 = pack2(-sa, -sa);
#pragma unroll
            for (int i = 0; i < 2; i++) {
                ulonglong2 x = Wp[i], y = Wq[i];
                ulonglong2 nx, ny;
                nx.x = fma2(ca2, x.x, mul2(nsa2, y.x));
                nx.y = fma2(ca2, x.y, mul2(nsa2, y.y));
                ny.x = fma2(sa2, x.x, mul2(ca2, y.x));
                ny.y = fma2(sa2, x.y, mul2(ca2, y.y));
                Wp[i] = nx; Wq[i] = ny;
            }
        }
        __syncthreads();
    }

    // Eigenvalues + top-RANK selection (tie-break by index -> deterministic)
    if (t < MATN) ev[t] = A[t * LDA + t];
    __syncthreads();
    if (t < MATN) {
        float e = ev[t]; int rk = 0;
        for (int j = 0; j < MATN; j++) {
            float o = ev[j];
            if (o > e || (o == e && j < t)) rk++;
        }
        if (rk < RANK) sidx[rk] = t;
    }
    __syncthreads();

    // P = V_sel V_selᵀ = Σ_r W[r,:]ᵀ W[r,:] over the 64 selected rows of W
    const int i0 = (t >> 5) * 4, j0 = (t & 31) * 4;
    float acc[4][4];
#pragma unroll
    for (int i = 0; i < 4; i++)
#pragma unroll
        for (int j = 0; j < 4; j++) acc[i][j] = 0.f;

    for (int ii = 0; ii < RANK; ii++) {
        int row = sidx[ii];
        const float* Wr = W + row * LDW;
        float4 va4 = *(const float4*)&Wr[i0];
        float4 vb4 = *(const float4*)&Wr[j0];
        float va[4] = {va4.x, va4.y, va4.z, va4.w};
        float vb[4] = {vb4.x, vb4.y, vb4.z, vb4.w};
#pragma unroll
        for (int i = 0; i < 4; i++)
#pragma unroll
            for (int j = 0; j < 4; j++) acc[i][j] += va[i] * vb[j];
    }
    float* Pp = &g_P[m][0][0];
#pragma unroll
    for (int i = 0; i < 4; i++) {
        float4 v = {acc[i][0], acc[i][1], acc[i][2], acc[i][3]};
        *(float4*)&Pp[(i0 + i) * MATN + j0] = v;
    }
}

// ---------------------------------------------------------------------------
// Kernel 3: Y = X · P  (grid: NM x 32 row-blocks of 64 rows, 256 threads)
// ---------------------------------------------------------------------------
#define LDX 129
#define REC_SMEM ((64 * LDX + MATN * MATN) * 4)

__global__ __launch_bounds__(256) void recon_kernel(const float* __restrict__ X,
                                                    float* __restrict__ out) {
    extern __shared__ float sm[];
    float* Xs = sm;              // 64 x 129
    float* Ps = sm + 64 * LDX;   // 128 x 128
    const int m = blockIdx.x, rb = blockIdx.y;
    const int t = threadIdx.x;

    const float* Xm = X + ((size_t)m * SLEN + (size_t)rb * 64) * MATN;
    for (int idx = t; idx < 64 * MATN; idx += 256) {
        int rI = idx >> 7, c = idx & 127;
        Xs[rI * LDX + c] = Xm[idx];
    }
    const float4* Pg = (const float4*)&g_P[m][0][0];
    float4* Pd = (float4*)Ps;
    for (int idx = t; idx < MATN * MATN / 4; idx += 256) Pd[idx] = Pg[idx];
    __syncthreads();

    const int r0 = (t >> 4) * 4, c0 = (t & 15) * 8;
    float acc[4][8];
#pragma unroll
    for (int i = 0; i < 4; i++)
#pragma unroll
        for (int j = 0; j < 8; j++) acc[i][j] = 0.f;

    for (int k = 0; k < MATN; k++) {
        float xv[4];
#pragma unroll
        for (int i = 0; i < 4; i++) xv[i] = Xs[(r0 + i) * LDX + k];
        float4 p0 = *(const float4*)&Ps[k * MATN + c0];
        float4 p1 = *(const float4*)&Ps[k * MATN + c0 + 4];
        float pv[8] = {p0.x, p0.y, p0.z, p0.w, p1.x, p1.y, p1.z, p1.w};
#pragma unroll
        for (int i = 0; i < 4; i++)
#pragma unroll
            for (int j = 0; j < 8; j++) acc[i][j] += xv[i] * pv[j];
    }

    float* Om = out + ((size_t)m * SLEN + (size_t)rb * 64) * MATN;
#pragma unroll
    for (int i = 0; i < 4; i++) {
        float4 v0 = {acc[i][0], acc[i][1], acc[i][2], acc[i][3]};
        float4 v1 = {acc[i][4], acc[i][5], acc[i][6], acc[i][7]};
        *(float4*)&Om[(r0 + i) * MATN + c0] = v0;
        *(float4*)&Om[(r0 + i) * MATN + c0 + 4] = v1;
    }
}

// ---------------------------------------------------------------------------
extern "C" void kernel_launch(void* const* d_in, const int* in_sizes, int n_in,
                              void* d_out, int out_size) {
    const float* X = (const float*)d_in[0];   // kv_cache fp32 (4,16,2048,128)
    float* out = (float*)d_out;               // fp32, same shape

    cudaFuncSetAttribute(jacobi_kernel, cudaFuncAttributeMaxDynamicSharedMemorySize, JAC_SMEM);
    cudaFuncSetAttribute(recon_kernel,  cudaFuncAttributeMaxDynamicSharedMemorySize, REC_SMEM);

    gram_kernel<<<dim3(NM, NPART), 256>>>(X);
    jacobi_kernel<<<NM, 1024, JAC_SMEM>>>();
    recon_kernel<<<dim3(NM, 32), 256, REC_SMEM>>>(X, out);
}

// round 9
// speedup vs baseline: 3.7632x; 1.4435x over previous
#include <cuda_runtime.h>
#include <math.h>
#include <stdint.h>

#define NM     64      // number of matrices (B*H)
#define MATN   128     // matrix dim (D)
#define SLEN   2048    // sequence length
#define RANK   64
#define SWEEPS 7
#define ROUNDS 127     // MATN - 1
#define TOTR   (SWEEPS * ROUNDS)
#define LDA    144     // A stride: 144 % 32 == 16 -> conflict-free (2 rows x 16 cols tiles)
#define LDW    132     // W stride: conflict-free float4 under (p + 2s) mapping
#define NPART  4       // gram split-K parts

// Scratch (device globals; no allocations allowed)
__device__ float g_G4[NPART][NM][MATN][MATN];  // partial Gram matrices (16 MB)
__device__ float g_P[NM][MATN][MATN];          // projectors (4 MB)

typedef unsigned long long u64t;
__device__ __forceinline__ u64t pack2(float lo, float hi) {
    u64t r; asm("mov.b64 %0,{%1,%2};" : "=l"(r) : "f"(lo), "f"(hi)); return r;
}
__device__ __forceinline__ u64t mul2(u64t a, u64t b) {
    u64t r; asm("mul.rn.f32x2 %0,%1,%2;" : "=l"(r) : "l"(a), "l"(b)); return r;
}
__device__ __forceinline__ u64t fma2(u64t a, u64t b, u64t c) {
    u64t r; asm("fma.rn.f32x2 %0,%1,%2,%3;" : "=l"(r) : "l"(a), "l"(b), "l"(c)); return r;
}

// ---- cluster / mbarrier helpers -------------------------------------------
__device__ __forceinline__ uint32_t ctarank() {
    uint32_t r; asm("mov.u32 %0, %%cluster_ctarank;" : "=r"(r)); return r;
}
__device__ __forceinline__ uint32_t mapa_rank(uint32_t laddr, uint32_t rank) {
    uint32_t r;
    asm("mapa.shared::cluster.u32 %0, %1, %2;" : "=r"(r) : "r"(laddr), "r"(rank));
    return r;
}
__device__ __forceinline__ void mbar_init(uint32_t a, uint32_t cnt) {
    asm volatile("mbarrier.init.shared.b64 [%0], %1;" :: "r"(a), "r"(cnt) : "memory");
}
__device__ __forceinline__ void mbar_arrive_remote(uint32_t remAddr) {
    asm volatile("mbarrier.arrive.shared::cluster.b64 _, [%0];" :: "r"(remAddr) : "memory");
}
__device__ __forceinline__ void fence_cluster() {
    asm volatile("fence.acq_rel.cluster;" ::: "memory");
}
__device__ __forceinline__ void mbar_wait(uint32_t addr, uint32_t parity) {
    asm volatile(
        "{\n\t"
        ".reg .pred P;\n"
        "WAIT_%=:\n\t"
        "mbarrier.try_wait.parity.acquire.cluster.shared::cta.b64 P, [%0], %1, 0x989680;\n\t"
        "@P bra.uni DONE_%=;\n\t"
        "bra.uni WAIT_%=;\n"
        "DONE_%=:\n\t"
        "}"
        :: "r"(addr), "r"(parity) : "memory");
}
__device__ __forceinline__ void st_cluster_f4(uint32_t addr, float4 v) {
    asm volatile("st.shared::cluster.v4.f32 [%0], {%1,%2,%3,%4};"
        :: "r"(addr), "f"(v.x), "f"(v.y), "f"(v.z), "f"(v.w) : "memory");
}
__device__ __forceinline__ void st_cluster_f(uint32_t addr, float v) {
    asm volatile("st.shared::cluster.f32 [%0], %1;" :: "r"(addr), "f"(v) : "memory");
}
#define CLUSTER_SYNC() do { \
    asm volatile("barrier.cluster.arrive.aligned;" ::: "memory"); \
    asm volatile("barrier.cluster.wait.aligned;" ::: "memory"); \
} while (0)

// Chess-tournament pairing: round rr in [0,127), pair index i in [0,64)
__device__ __forceinline__ void pair_pq(int i, int rr, int& p, int& q) {
    if (i == 0) { p = 0; }
    else { int x = i - 1 + rr; if (x >= 127) x -= 127; p = 1 + x; }
    int y = 126 - i + rr; if (y >= 127) y -= 127; q = 1 + y;
}

// Jacobi rotation for pair i at round rr, from A (stride LDA)
__device__ __forceinline__ void jac_rot(const float* A, int rr, int i,
                                        float& c, float& s, int& p, int& q) {
    pair_pq(i, rr, p, q);
    float app = A[p * LDA + p], aqq = A[q * LDA + q], apq = A[p * LDA + q];
    c = 1.f; s = 0.f;
    float scl = fabsf(app) + fabsf(aqq);
    if (fabsf(apq) > 1e-12f * scl + 1e-38f) {
        float tau = (aqq - app) / (2.f * apq);
        float tt = 1.f / (fabsf(tau) + sqrtf(1.f + tau * tau));
        tt = (tau < 0.f) ? -tt : tt;
        c = rsqrtf(1.f + tt * tt);
        s = tt * c;
    }
}

// ---------------------------------------------------------------------------
// Kernel 1: partial Gram  G_part = X_partᵀ X_part   (grid: NM x NPART, 256 thr)
// ---------------------------------------------------------------------------
__global__ __launch_bounds__(256) void gram_kernel(const float* __restrict__ X) {
    __shared__ float Xs[64][MATN];
    const int m = blockIdx.x, part = blockIdx.y;
    const int t = threadIdx.x;
    const int a0 = (t >> 4) * 8, b0 = (t & 15) * 8;
    float acc[8][8];
#pragma unroll
    for (int i = 0; i < 8; i++)
#pragma unroll
        for (int j = 0; j < 8; j++) acc[i][j] = 0.f;

    const float* Xm = X + ((size_t)m * SLEN + (size_t)part * 512) * MATN;
    for (int ch = 0; ch < 8; ch++) {
        const float4* src = (const float4*)(Xm + (size_t)ch * 64 * MATN);
        float4* dst = (float4*)&Xs[0][0];
#pragma unroll
        for (int j = 0; j < 8; j++) dst[t + 256 * j] = src[t + 256 * j];
        __syncthreads();
#pragma unroll 4
        for (int s = 0; s < 64; s++) {
            float4 a40 = *(const float4*)&Xs[s][a0];
            float4 a41 = *(const float4*)&Xs[s][a0 + 4];
            float4 b40 = *(const float4*)&Xs[s][b0];
            float4 b41 = *(const float4*)&Xs[s][b0 + 4];
            float av[8] = {a40.x, a40.y, a40.z, a40.w, a41.x, a41.y, a41.z, a41.w};
            float bv[8] = {b40.x, b40.y, b40.z, b40.w, b41.x, b41.y, b41.z, b41.w};
#pragma unroll
            for (int i = 0; i < 8; i++)
#pragma unroll
                for (int j = 0; j < 8; j++) acc[i][j] += av[i] * bv[j];
        }
        __syncthreads();
    }
    float* Gp = &g_G4[part][m][0][0];
#pragma unroll
    for (int i = 0; i < 8; i++) {
        float4 v0 = {acc[i][0], acc[i][1], acc[i][2], acc[i][3]};
        float4 v1 = {acc[i][4], acc[i][5], acc[i][6], acc[i][7]};
        *(float4*)&Gp[(a0 + i) * MATN + b0] = v0;
        *(float4*)&Gp[(a0 + i) * MATN + b0 + 4] = v1;
    }
}

// ---------------------------------------------------------------------------
// Kernel 2: Jacobi eigensolver, 2-CTA cluster per matrix.
//   CTA rank 0: holds A; computes rotations (phase 0) + A update (phase 1a).
//   CTA rank 1: holds W = Vᵀ; applies rotations (phase 1b); builds projector.
// Rotations ship CTA0 -> CTA1 via DSMEM, double-buffered, mbarrier handshake.
// smem byte layout (identical in both CTAs):
//   [0,2048)    rot[2][64] float4
//   [2048,2064) fullb[2]  (mbarriers; used in CTA1)
//   [2064,2080) emptyb[2] (mbarriers; used in CTA0)
//   [2080,2592) ev[128]
//   [2592,2848) sidx[64]
//   [3072, ...) big[]: A (128x144) in CTA0 / W (128x132) in CTA1
// ---------------------------------------------------------------------------
#define BAR_FULL  2048
#define BAR_EMPTY 2064
#define EV_OFF    2080
#define SIDX_OFF  2592
#define BIG_OFF   3072
#define JAC_SMEM  (BIG_OFF + MATN * LDA * 4)

__global__ __launch_bounds__(1024) __cluster_dims__(2, 1, 1)
void jacobi_kernel() {
    extern __shared__ float smf[];
    char* smb = (char*)smf;
    float4* rot  = (float4*)smb;
    float*  ev   = (float*)(smb + EV_OFF);
    int*    sidx = (int*)(smb + SIDX_OFF);
    float*  big  = (float*)(smb + BIG_OFF);

    const int m = blockIdx.y, t = threadIdx.x;
    const uint32_t rank = ctarank();
    const uint32_t sbase = (uint32_t)__cvta_generic_to_shared(smb);

    // Init local mbarriers (each CTA inits all 4; only relevant ones used)
    if (t == 0) {
        mbar_init(sbase + BAR_FULL, 1);
        mbar_init(sbase + BAR_FULL + 8, 1);
        mbar_init(sbase + BAR_EMPTY, 1);
        mbar_init(sbase + BAR_EMPTY + 8, 1);
    }
    __syncthreads();
    CLUSTER_SYNC();   // barriers visible cluster-wide before any remote arrive

    const int pa  = t >> 4;   // pair index (0..63)
    const int sub = t & 15;   // sub-slot (0..15)

    if (rank == 0) {
        // ===== A-CTA =====
        for (int idx = t; idx < MATN * MATN; idx += 1024) {
            int i = idx >> 7, j = idx & 127;
            big[i * LDA + j] = g_G4[0][m][i][j] + g_G4[1][m][i][j]
                             + g_G4[2][m][i][j] + g_G4[3][m][i][j];
        }
        __syncthreads();

        // Prologue: rot(0) -> local slot0 + remote slot0
        if (t < 64) {
            float c, s; int p, q;
            jac_rot(big, 0, t, c, s, p, q);
            float4 v = make_float4(c, s, __int_as_float(p), __int_as_float(q));
            rot[t] = v;
            st_cluster_f4(mapa_rank(sbase + t * 16, 1), v);
        }
        __syncthreads();
        if (t == 0) { fence_cluster(); mbar_arrive_remote(mapa_rank(sbase + BAR_FULL, 1)); }

        int phE0 = 0, phE1 = 1;   // producer empty-parity per slot (slot1 first wait passes)

        for (int r = 0; r < TOTR; r++) {
            float4* rots = rot + ((r & 1) << 6);

            float4 ra = rots[pa];
            const float ca = ra.x, sa = ra.y;
            const int p_a = __float_as_int(ra.z), q_a = __float_as_int(ra.w);
            float* Arp = big + p_a * LDA;
            float* Arq = big + q_a * LDA;

            // Phase 1a: fused 2x2 closure-block update A' = JᵀAJ
#pragma unroll
            for (int k = 0; k < 4; k++) {
                int bp = sub + (k << 4);
                float4 rb = rots[bp];
                float cb = rb.x, sb = rb.y;
                int p_b = __float_as_int(rb.z), q_b = __float_as_int(rb.w);
                float m00 = Arp[p_b], m01 = Arp[q_b];
                float m10 = Arq[p_b], m11 = Arq[q_b];
                float r00 = ca * m00 - sa * m10, r01 = ca * m01 - sa * m11;
                float r10 = sa * m00 + ca * m10, r11 = sa * m01 + ca * m11;
                Arp[p_b] = cb * r00 - sb * r01;
                Arp[q_b] = sb * r00 + cb * r01;
                Arq[p_b] = cb * r10 - sb * r11;
                Arq[q_b] = sb * r10 + cb * r11;
            }
            __syncthreads();

            if (r + 1 < TOTR) {
                int s = (r + 1) & 1;
                if (t < 64) {
                    int par = s ? phE1 : phE0;
                    mbar_wait(sbase + BAR_EMPTY + s * 8, par);   // CTA1 done with this slot
                    if (s) phE1 ^= 1; else phE0 ^= 1;
                    float c, sn; int p, q;
                    int rr1 = r + 1; rr1 -= (rr1 / ROUNDS) * ROUNDS;
                    jac_rot(big, rr1, t, c, sn, p, q);
                    float4 v = make_float4(c, sn, __int_as_float(p), __int_as_float(q));
                    rot[(s << 6) + t] = v;
                    st_cluster_f4(mapa_rank(sbase + ((s << 6) + t) * 16, 1), v);
                }
                __syncthreads();
                if (t == 0) { fence_cluster(); mbar_arrive_remote(mapa_rank(sbase + BAR_FULL + s * 8, 1)); }
            }
        }

        // Ship eigenvalue diagonal to CTA1
        if (t < MATN) {
            float e = big[t * LDA + t];
            st_cluster_f(mapa_rank(sbase + EV_OFF + t * 4, 1), e);
        }
        CLUSTER_SYNC();   // arrive.release publishes ev; CTA1's wait acquires
    } else {
        // ===== W-CTA =====
        for (int idx = t; idx < MATN * MATN; idx += 1024) {
            int i = idx >> 7, j = idx & 127;
            big[i * LDW + j] = (i == j) ? 1.f : 0.f;
        }
        __syncthreads();

        int phF0 = 0, phF1 = 0;   // consumer full-parity per slot

        for (int r = 0; r < TOTR; r++) {
            int s = r & 1;
            if (t == 0) {
                int par = s ? phF1 : phF0;
                mbar_wait(sbase + BAR_FULL + s * 8, par);
                if (s) phF1 ^= 1; else phF0 ^= 1;
            }
            __syncthreads();

            float4 ra = rot[(s << 6) + pa];
            __syncthreads();   // all rot reads done before releasing the slot
            if (t == 0) mbar_arrive_remote(mapa_rank(sbase + BAR_EMPTY + s * 8, 0));

            const float ca = ra.x, sa = ra.y;
            const int p_a = __float_as_int(ra.z), q_a = __float_as_int(ra.w);

            // Phase 1b: W = Vᵀ row rotation, packed f32x2 (8 cols per thread)
            ulonglong2* Wp = (ulonglong2*)(big + p_a * LDW + (sub << 3));
            ulonglong2* Wq = (ulonglong2*)(big + q_a * LDW + (sub << 3));
            const u64t ca2  = pack2(ca, ca);
            const u64t sa2  = pack2(sa, sa);
            const u64t nsa2 = pack2(-sa, -sa);
#pragma unroll
            for (int i = 0; i < 2; i++) {
                ulonglong2 x = Wp[i], y = Wq[i];
                ulonglong2 nx, ny;
                nx.x = fma2(ca2, x.x, mul2(nsa2, y.x));
                nx.y = fma2(ca2, x.y, mul2(nsa2, y.y));
                ny.x = fma2(sa2, x.x, mul2(ca2, y.x));
                ny.y = fma2(sa2, x.y, mul2(ca2, y.y));
                Wp[i] = nx; Wq[i] = ny;
            }
            // no trailing bar: next round's wait+bar orders 1b(r) before 1b(r+1)
        }

        CLUSTER_SYNC();   // ev now visible locally

        // Top-RANK selection (tie-break by index -> deterministic)
        if (t < MATN) {
            float e = ev[t]; int rk = 0;
            for (int j = 0; j < MATN; j++) {
                float o = ev[j];
                if (o > e || (o == e && j < t)) rk++;
            }
            if (rk < RANK) sidx[rk] = t;
        }
        __syncthreads();

        // P = Σ over 64 selected rows of W: W[r,:]ᵀ W[r,:]
        const int i0 = (t >> 5) * 4, j0 = (t & 31) * 4;
        float acc[4][4];
#pragma unroll
        for (int i = 0; i < 4; i++)
#pragma unroll
            for (int j = 0; j < 4; j++) acc[i][j] = 0.f;

        for (int ii = 0; ii < RANK; ii++) {
            int row = sidx[ii];
            const float* Wr = big + row * LDW;
            float4 va4 = *(const float4*)&Wr[i0];
            float4 vb4 = *(const float4*)&Wr[j0];
            float va[4] = {va4.x, va4.y, va4.z, va4.w};
            float vb[4] = {vb4.x, vb4.y, vb4.z, vb4.w};
#pragma unroll
            for (int i = 0; i < 4; i++)
#pragma unroll
                for (int j = 0; j < 4; j++) acc[i][j] += va[i] * vb[j];
        }
        float* Pp = &g_P[m][0][0];
#pragma unroll
        for (int i = 0; i < 4; i++) {
            float4 v = {acc[i][0], acc[i][1], acc[i][2], acc[i][3]};
            *(float4*)&Pp[(i0 + i) * MATN + j0] = v;
        }
    }
}

// ---------------------------------------------------------------------------
// Kernel 3: Y = X · P  (grid: NM x 32 row-blocks of 64 rows, 256 threads)
// ---------------------------------------------------------------------------
#define LDX 129
#define REC_SMEM ((64 * LDX + MATN * MATN) * 4)

__global__ __launch_bounds__(256) void recon_kernel(const float* __restrict__ X,
                                                    float* __restrict__ out) {
    extern __shared__ float sm[];
    float* Xs = sm;              // 64 x 129
    float* Ps = sm + 64 * LDX;   // 128 x 128
    const int m = blockIdx.x, rb = blockIdx.y;
    const int t = threadIdx.x;

    const float* Xm = X + ((size_t)m * SLEN + (size_t)rb * 64) * MATN;
    for (int idx = t; idx < 64 * MATN; idx += 256) {
        int rI = idx >> 7, c = idx & 127;
        Xs[rI * LDX + c] = Xm[idx];
    }
    const float4* Pg = (const float4*)&g_P[m][0][0];
    float4* Pd = (float4*)Ps;
    for (int idx = t; idx < MATN * MATN / 4; idx += 256) Pd[idx] = Pg[idx];
    __syncthreads();

    const int r0 = (t >> 4) * 4, c0 = (t & 15) * 8;
    float acc[4][8];
#pragma unroll
    for (int i = 0; i < 4; i++)
#pragma unroll
        for (int j = 0; j < 8; j++) acc[i][j] = 0.f;

    for (int k = 0; k < MATN; k++) {
        float xv[4];
#pragma unroll
        for (int i = 0; i < 4; i++) xv[i] = Xs[(r0 + i) * LDX + k];
        float4 p0 = *(const float4*)&Ps[k * MATN + c0];
        float4 p1 = *(const float4*)&Ps[k * MATN + c0 + 4];
        float pv[8] = {p0.x, p0.y, p0.z, p0.w, p1.x, p1.y, p1.z, p1.w};
#pragma unroll
        for (int i = 0; i < 4; i++)
#pragma unroll
            for (int j = 0; j < 8; j++) acc[i][j] += xv[i] * pv[j];
    }

    float* Om = out + ((size_t)m * SLEN + (size_t)rb * 64) * MATN;
#pragma unroll
    for (int i = 0; i < 4; i++) {
        float4 v0 = {acc[i][0], acc[i][1], acc[i][2], acc[i][3]};
        float4 v1 = {acc[i][4], acc[i][5], acc[i][6], acc[i][7]};
        *(float4*)&Om[(r0 + i) * MATN + c0] = v0;
        *(float4*)&Om[(r0 + i) * MATN + c0 + 4] = v1;
    }
}

// ---------------------------------------------------------------------------
extern "C" void kernel_launch(void* const* d_in, const int* in_sizes, int n_in,
                              void* d_out, int out_size) {
    const float* X = (const float*)d_in[0];   // kv_cache fp32 (4,16,2048,128)
    float* out = (float*)d_out;               // fp32, same shape

    cudaFuncSetAttribute(jacobi_kernel, cudaFuncAttributeMaxDynamicSharedMemorySize, JAC_SMEM);
    cudaFuncSetAttribute(recon_kernel,  cudaFuncAttributeMaxDynamicSharedMemorySize, REC_SMEM);

    gram_kernel<<<dim3(NM, NPART), 256>>>(X);
    jacobi_kernel<<<dim3(2, NM), 1024, JAC_SMEM>>>();
    recon_kernel<<<dim3(NM, 32), 256, REC_SMEM>>>(X, out);
}

// round 10
// speedup vs baseline: 3.8963x; 1.0354x over previous
#include <cuda_runtime.h>
#include <math.h>
#include <stdint.h>

#define NM     64      // number of matrices (B*H)
#define MATN   128     // matrix dim (D)
#define SLEN   2048    // sequence length
#define RANK   64
#define SWEEPS 7
#define ROUNDS 127     // MATN - 1
#define TOTR   (SWEEPS * ROUNDS)
#define LDA    144     // A stride: 144 % 32 == 16 -> conflict-free (2 rows x 16 cols tiles)
#define LDW    132     // W stride: conflict-free float4 under (p + 2s) mapping
#define NPART  8       // gram split-K parts

// Scratch (device globals; no allocations allowed)
__device__ float g_G4[NPART][NM][MATN][MATN];  // partial Gram matrices (32 MB)
__device__ float g_P[NM][MATN][MATN];          // projectors (4 MB)

typedef unsigned long long u64t;
__device__ __forceinline__ u64t pack2(float lo, float hi) {
    u64t r; asm("mov.b64 %0,{%1,%2};" : "=l"(r) : "f"(lo), "f"(hi)); return r;
}
__device__ __forceinline__ void unpack2(u64t v, float& lo, float& hi) {
    asm("mov.b64 {%0,%1}, %2;" : "=f"(lo), "=f"(hi) : "l"(v));
}
__device__ __forceinline__ u64t mul2(u64t a, u64t b) {
    u64t r; asm("mul.rn.f32x2 %0,%1,%2;" : "=l"(r) : "l"(a), "l"(b)); return r;
}
__device__ __forceinline__ u64t fma2(u64t a, u64t b, u64t c) {
    u64t r; asm("fma.rn.f32x2 %0,%1,%2,%3;" : "=l"(r) : "l"(a), "l"(b), "l"(c)); return r;
}

// ---- cluster / mbarrier helpers -------------------------------------------
__device__ __forceinline__ uint32_t ctarank() {
    uint32_t r; asm("mov.u32 %0, %%cluster_ctarank;" : "=r"(r)); return r;
}
__device__ __forceinline__ uint32_t mapa_rank(uint32_t laddr, uint32_t rank) {
    uint32_t r;
    asm("mapa.shared::cluster.u32 %0, %1, %2;" : "=r"(r) : "r"(laddr), "r"(rank));
    return r;
}
__device__ __forceinline__ void mbar_init(uint32_t a, uint32_t cnt) {
    asm volatile("mbarrier.init.shared.b64 [%0], %1;" :: "r"(a), "r"(cnt) : "memory");
}
__device__ __forceinline__ void mbar_arrive_remote(uint32_t remAddr) {
    asm volatile("mbarrier.arrive.shared::cluster.b64 _, [%0];" :: "r"(remAddr) : "memory");
}
__device__ __forceinline__ void mbar_arrive_expect_tx(uint32_t addr, uint32_t bytes) {
    asm volatile("mbarrier.arrive.expect_tx.shared::cta.b64 _, [%0], %1;"
                 :: "r"(addr), "r"(bytes) : "memory");
}
__device__ __forceinline__ void mbar_wait(uint32_t addr, uint32_t parity) {
    asm volatile(
        "{\n\t"
        ".reg .pred P;\n"
        "WAIT_%=:\n\t"
        "mbarrier.try_wait.parity.acquire.cluster.shared::cta.b64 P, [%0], %1, 0x989680;\n\t"
        "@P bra.uni DONE_%=;\n\t"
        "bra.uni WAIT_%=;\n"
        "DONE_%=:\n\t"
        "}"
        :: "r"(addr), "r"(parity) : "memory");
}
// st.async: write 16B into peer-CTA smem, tx-signaling the peer's mbarrier.
__device__ __forceinline__ void st_async_f4(uint32_t remAddr, float4 v, uint32_t remMbar) {
    asm volatile(
        "st.async.shared::cluster.mbarrier::complete_tx::bytes.v4.f32 [%0], {%1,%2,%3,%4}, [%5];"
        :: "r"(remAddr), "f"(v.x), "f"(v.y), "f"(v.z), "f"(v.w), "r"(remMbar) : "memory");
}
__device__ __forceinline__ void st_cluster_f(uint32_t addr, float v) {
    asm volatile("st.shared::cluster.f32 [%0], %1;" :: "r"(addr), "f"(v) : "memory");
}
#define CLUSTER_SYNC() do { \
    asm volatile("barrier.cluster.arrive.aligned;" ::: "memory"); \
    asm volatile("barrier.cluster.wait.aligned;" ::: "memory"); \
} while (0)

// Chess-tournament pairing: round rr in [0,127), pair index i in [0,64)
__device__ __forceinline__ void pair_pq(int i, int rr, int& p, int& q) {
    if (i == 0) { p = 0; }
    else { int x = i - 1 + rr; if (x >= 127) x -= 127; p = 1 + x; }
    int y = 126 - i + rr; if (y >= 127) y -= 127; q = 1 + y;
}

// Jacobi rotation for pair i at round rr, from A (stride LDA)
__device__ __forceinline__ void jac_rot(const float* A, int rr, int i,
                                        float& c, float& s, int& p, int& q) {
    pair_pq(i, rr, p, q);
    float app = A[p * LDA + p], aqq = A[q * LDA + q], apq = A[p * LDA + q];
    c = 1.f; s = 0.f;
    float scl = fabsf(app) + fabsf(aqq);
    if (fabsf(apq) > 1e-12f * scl + 1e-38f) {
        float tau = (aqq - app) / (2.f * apq);
        float tt = 1.f / (fabsf(tau) + sqrtf(1.f + tau * tau));
        tt = (tau < 0.f) ? -tt : tt;
        c = rsqrtf(1.f + tt * tt);
        s = tt * c;
    }
}

// ---------------------------------------------------------------------------
// Kernel 1: partial Gram  G_part = X_partᵀ X_part   (grid: NM x NPART, 256 thr)
// ---------------------------------------------------------------------------
__global__ __launch_bounds__(256) void gram_kernel(const float* __restrict__ X) {
    __shared__ float Xs[64][MATN];
    const int m = blockIdx.x, part = blockIdx.y;
    const int t = threadIdx.x;
    const int a0 = (t >> 4) * 8, b0 = (t & 15) * 8;
    float acc[8][8];
#pragma unroll
    for (int i = 0; i < 8; i++)
#pragma unroll
        for (int j = 0; j < 8; j++) acc[i][j] = 0.f;

    const float* Xm = X + ((size_t)m * SLEN + (size_t)part * (SLEN / NPART)) * MATN;
    for (int ch = 0; ch < SLEN / NPART / 64; ch++) {
        const float4* src = (const float4*)(Xm + (size_t)ch * 64 * MATN);
        float4* dst = (float4*)&Xs[0][0];
#pragma unroll
        for (int j = 0; j < 8; j++) dst[t + 256 * j] = src[t + 256 * j];
        __syncthreads();
#pragma unroll 4
        for (int s = 0; s < 64; s++) {
            float4 a40 = *(const float4*)&Xs[s][a0];
            float4 a41 = *(const float4*)&Xs[s][a0 + 4];
            float4 b40 = *(const float4*)&Xs[s][b0];
            float4 b41 = *(const float4*)&Xs[s][b0 + 4];
            float av[8] = {a40.x, a40.y, a40.z, a40.w, a41.x, a41.y, a41.z, a41.w};
            float bv[8] = {b40.x, b40.y, b40.z, b40.w, b41.x, b41.y, b41.z, b41.w};
#pragma unroll
            for (int i = 0; i < 8; i++)
#pragma unroll
                for (int j = 0; j < 8; j++) acc[i][j] += av[i] * bv[j];
        }
        __syncthreads();
    }
    float* Gp = &g_G4[part][m][0][0];
#pragma unroll
    for (int i = 0; i < 8; i++) {
        float4 v0 = {acc[i][0], acc[i][1], acc[i][2], acc[i][3]};
        float4 v1 = {acc[i][4], acc[i][5], acc[i][6], acc[i][7]};
        *(float4*)&Gp[(a0 + i) * MATN + b0] = v0;
        *(float4*)&Gp[(a0 + i) * MATN + b0 + 4] = v1;
    }
}

// ---------------------------------------------------------------------------
// Kernel 2: Jacobi eigensolver, 2-CTA cluster per matrix.
//   CTA rank 0: holds A; computes rotations (phase 0) + A update (phase 1a).
//   CTA rank 1: holds W = Vᵀ; applies rotations (phase 1b); builds projector.
// Rotations ship CTA0 -> CTA1 via st.async (tx-count mbarrier completion),
// double-buffered; backpressure via plain-arrive empty barriers.
// smem byte layout (identical in both CTAs):
//   [0,2048)    rot[2][64] float4
//   [2048,2064) fullb[2]  (tx mbarriers; live in CTA1)
//   [2064,2080) emptyb[2] (mbarriers; live in CTA0)
//   [2080,2592) ev[128]
//   [2592,2848) sidx[64]
//   [3072, ...) big[]: A (128x144) in CTA0 / W (128x132) in CTA1
// ---------------------------------------------------------------------------
#define BAR_FULL  2048
#define BAR_EMPTY 2064
#define EV_OFF    2080
#define SIDX_OFF  2592
#define BIG_OFF   3072
#define JAC_SMEM  (BIG_OFF + MATN * LDA * 4)

__global__ __launch_bounds__(1024) __cluster_dims__(2, 1, 1)
void jacobi_kernel() {
    extern __shared__ float smf[];
    char* smb = (char*)smf;
    float4* rot  = (float4*)smb;
    float*  ev   = (float*)(smb + EV_OFF);
    int*    sidx = (int*)(smb + SIDX_OFF);
    float*  big  = (float*)(smb + BIG_OFF);

    const int m = blockIdx.y, t = threadIdx.x;
    const uint32_t rank = ctarank();
    const uint32_t sbase = (uint32_t)__cvta_generic_to_shared(smb);

    // Init mbarriers; CTA1 pre-arms both full slots (count=1 arrive + 1024B tx)
    if (t == 0) {
        mbar_init(sbase + BAR_FULL, 1);
        mbar_init(sbase + BAR_FULL + 8, 1);
        mbar_init(sbase + BAR_EMPTY, 1);
        mbar_init(sbase + BAR_EMPTY + 8, 1);
        if (rank == 1) {
            mbar_arrive_expect_tx(sbase + BAR_FULL, 1024);
            mbar_arrive_expect_tx(sbase + BAR_FULL + 8, 1024);
        }
    }
    __syncthreads();
    CLUSTER_SYNC();   // barriers visible cluster-wide before any remote op

    const int pa  = t >> 4;   // pair index (0..63)
    const int sub = t & 15;   // sub-slot (0..15)

    if (rank == 0) {
        // ===== A-CTA =====
        for (int idx = t; idx < MATN * MATN; idx += 1024) {
            int i = idx >> 7, j = idx & 127;
            float a = 0.f;
#pragma unroll
            for (int pp = 0; pp < NPART; pp++) a += g_G4[pp][m][i][j];
            big[i * LDA + j] = a;
        }
        __syncthreads();

        // Prologue: rot(0) -> local slot0 + remote slot0 (st.async, tx-signal)
        if (t < 64) {
            float c, s; int p, q;
            jac_rot(big, 0, t, c, s, p, q);
            float4 v = make_float4(c, s, __int_as_float(p), __int_as_float(q));
            rot[t] = v;
            st_async_f4(mapa_rank(sbase + t * 16, 1), v,
                        mapa_rank(sbase + BAR_FULL, 1));
        }
        __syncthreads();

        int phE0 = 0, phE1 = 1;   // producer empty-parity per slot (slot1 first wait passes)

        for (int r = 0; r < TOTR; r++) {
            float4* rots = rot + ((r & 1) << 6);

            float4 ra = rots[pa];
            const float ca = ra.x, sa = ra.y;
            const int p_a = __float_as_int(ra.z), q_a = __float_as_int(ra.w);
            float* Arp = big + p_a * LDA;
            float* Arq = big + q_a * LDA;
            const u64t ca2  = pack2(ca, ca);
            const u64t sa2  = pack2(sa, sa);
            const u64t nsa2 = pack2(-sa, -sa);

            // Phase 1a: fused 2x2 closure-block update A' = JᵀAJ
            // stage1 (row rotation) in packed f32x2, stage2 (col rotation) scalar
#pragma unroll
            for (int k = 0; k < 4; k++) {
                int bp = sub + (k << 4);
                float4 rb = rots[bp];
                float cb = rb.x, sb = rb.y;
                int p_b = __float_as_int(rb.z), q_b = __float_as_int(rb.w);
                float m00 = Arp[p_b], m01 = Arp[q_b];
                float m10 = Arq[p_b], m11 = Arq[q_b];
                u64t mp = pack2(m00, m01), mq = pack2(m10, m11);
                u64t rp = fma2(ca2, mp, mul2(nsa2, mq));
                u64t rq = fma2(sa2, mp, mul2(ca2, mq));
                float r00, r01, r10, r11;
                unpack2(rp, r00, r01);
                unpack2(rq, r10, r11);
                Arp[p_b] = cb * r00 - sb * r01;
                Arp[q_b] = sb * r00 + cb * r01;
                Arq[p_b] = cb * r10 - sb * r11;
                Arq[q_b] = sb * r10 + cb * r11;
            }
            __syncthreads();

            if (r + 1 < TOTR) {
                int s = (r + 1) & 1;
                if (t < 64) {
                    int par = s ? phE1 : phE0;
                    mbar_wait(sbase + BAR_EMPTY + s * 8, par);   // CTA1 done with this slot
                    if (s) phE1 ^= 1; else phE0 ^= 1;
                    float c, sn; int p, q;
                    int rr1 = r + 1; rr1 -= (rr1 / ROUNDS) * ROUNDS;
                    jac_rot(big, rr1, t, c, sn, p, q);
                    float4 v = make_float4(c, sn, __int_as_float(p), __int_as_float(q));
                    rot[(s << 6) + t] = v;
                    st_async_f4(mapa_rank(sbase + ((s << 6) + t) * 16, 1), v,
                                mapa_rank(sbase + BAR_FULL + s * 8, 1));
                }
                __syncthreads();   // local rot slot visible to next round's 1a
            }
        }

        // Ship eigenvalue diagonal to CTA1
        if (t < MATN) {
            float e = big[t * LDA + t];
            st_cluster_f(mapa_rank(sbase + EV_OFF + t * 4, 1), e);
        }
        CLUSTER_SYNC();   // arrive.release publishes ev; CTA1's wait acquires
    } else {
        // ===== W-CTA =====
        for (int idx = t; idx < MATN * MATN; idx += 1024) {
            int i = idx >> 7, j = idx & 127;
            big[i * LDW + j] = (i == j) ? 1.f : 0.f;
        }
        __syncthreads();

        int phF0 = 0, phF1 = 0;   // consumer full-parity per slot

        for (int r = 0; r < TOTR; r++) {
            int s = r & 1;
            {
                int par = s ? phF1 : phF0;
                mbar_wait(sbase + BAR_FULL + s * 8, par);   // ALL threads
                if (s) phF1 ^= 1; else phF0 ^= 1;
            }
            if (t == 0)   // re-arm this slot for its next use (phase already flipped)
                mbar_arrive_expect_tx(sbase + BAR_FULL + s * 8, 1024);

            float4 ra = rot[(s << 6) + pa];
            __syncthreads();   // all rot reads done before releasing the slot
            if (t == 0) mbar_arrive_remote(mapa_rank(sbase + BAR_EMPTY + s * 8, 0));

            const float ca = ra.x, sa = ra.y;
            const int p_a = __float_as_int(ra.z), q_a = __float_as_int(ra.w);

            // Phase 1b: W = Vᵀ row rotation, packed f32x2 (8 cols per thread)
            ulonglong2* Wp = (ulonglong2*)(big + p_a * LDW + (sub << 3));
            ulonglong2* Wq = (ulonglong2*)(big + q_a * LDW + (sub << 3));
            const u64t ca2  = pack2(ca, ca);
            const u64t sa2  = pack2(sa, sa);
            const u64t nsa2 = pack2(-sa, -sa);
#pragma unroll
            for (int i = 0; i < 2; i++) {
                ulonglong2 x = Wp[i], y = Wq[i];
                ulonglong2 nx, ny;
                nx.x = fma2(ca2, x.x, mul2(nsa2, y.x));
                nx.y = fma2(ca2, x.y, mul2(nsa2, y.y));
                ny.x = fma2(sa2, x.x, mul2(ca2, y.x));
                ny.y = fma2(sa2, x.y, mul2(ca2, y.y));
                Wp[i] = nx; Wq[i] = ny;
            }
            // no trailing bar: next round's wait orders 1b(r) before 1b(r+1)
        }

        CLUSTER_SYNC();   // ev now visible locally

        // Top-RANK selection (tie-break by index -> deterministic)
        if (t < MATN) {
            float e = ev[t]; int rk = 0;
            for (int j = 0; j < MATN; j++) {
                float o = ev[j];
                if (o > e || (o == e && j < t)) rk++;
            }
            if (rk < RANK) sidx[rk] = t;
        }
        __syncthreads();

        // P = Σ over 64 selected rows of W: W[r,:]ᵀ W[r,:]
        const int i0 = (t >> 5) * 4, j0 = (t & 31) * 4;
        float acc[4][4];
#pragma unroll
        for (int i = 0; i < 4; i++)
#pragma unroll
            for (int j = 0; j < 4; j++) acc[i][j] = 0.f;

        for (int ii = 0; ii < RANK; ii++) {
            int row = sidx[ii];
            const float* Wr = big + row * LDW;
            float4 va4 = *(const float4*)&Wr[i0];
            float4 vb4 = *(const float4*)&Wr[j0];
            float va[4] = {va4.x, va4.y, va4.z, va4.w};
            float vb[4] = {vb4.x, vb4.y, vb4.z, vb4.w};
#pragma unroll
            for (int i = 0; i < 4; i++)
#pragma unroll
                for (int j = 0; j < 4; j++) acc[i][j] += va[i] * vb[j];
        }
        float* Pp = &g_P[m][0][0];
#pragma unroll
        for (int i = 0; i < 4; i++) {
            float4 v = {acc[i][0], acc[i][1], acc[i][2], acc[i][3]};
            *(float4*)&Pp[(i0 + i) * MATN + j0] = v;
        }
    }
}

// ---------------------------------------------------------------------------
// Kernel 3: Y = X · P  (grid: NM x 32 row-blocks of 64 rows, 256 threads)
// ---------------------------------------------------------------------------
#define LDX 129
#define REC_SMEM ((64 * LDX + MATN * MATN) * 4)

__global__ __launch_bounds__(256) void recon_kernel(const float* __restrict__ X,
                                                    float* __restrict__ out) {
    extern __shared__ float sm[];
    float* Xs = sm;              // 64 x 129
    float* Ps = sm + 64 * LDX;   // 128 x 128
    const int m = blockIdx.x, rb = blockIdx.y;
    const int t = threadIdx.x;

    const float* Xm = X + ((size_t)m * SLEN + (size_t)rb * 64) * MATN;
    for (int idx = t; idx < 64 * MATN; idx += 256) {
        int rI = idx >> 7, c = idx & 127;
        Xs[rI * LDX + c] = Xm[idx];
    }
    const float4* Pg = (const float4*)&g_P[m][0][0];
    float4* Pd = (float4*)Ps;
    for (int idx = t; idx < MATN * MATN / 4; idx += 256) Pd[idx] = Pg[idx];
    __syncthreads();

    const int r0 = (t >> 4) * 4, c0 = (t & 15) * 8;
    float acc[4][8];
#pragma unroll
    for (int i = 0; i < 4; i++)
#pragma unroll
        for (int j = 0; j < 8; j++) acc[i][j] = 0.f;

    for (int k = 0; k < MATN; k++) {
        float xv[4];
#pragma unroll
        for (int i = 0; i < 4; i++) xv[i] = Xs[(r0 + i) * LDX + k];
        float4 p0 = *(const float4*)&Ps[k * MATN + c0];
        float4 p1 = *(const float4*)&Ps[k * MATN + c0 + 4];
        float pv[8] = {p0.x, p0.y, p0.z, p0.w, p1.x, p1.y, p1.z, p1.w};
#pragma unroll
        for (int i = 0; i < 4; i++)
#pragma unroll
            for (int j = 0; j < 8; j++) acc[i][j] += xv[i] * pv[j];
    }

    float* Om = out + ((size_t)m * SLEN + (size_t)rb * 64) * MATN;
#pragma unroll
    for (int i = 0; i < 4; i++) {
        float4 v0 = {acc[i][0], acc[i][1], acc[i][2], acc[i][3]};
        float4 v1 = {acc[i][4], acc[i][5], acc[i][6], acc[i][7]};
        *(float4*)&Om[(r0 + i) * MATN + c0] = v0;
        *(float4*)&Om[(r0 + i) * MATN + c0 + 4] = v1;
    }
}

// ---------------------------------------------------------------------------
extern "C" void kernel_launch(void* const* d_in, const int* in_sizes, int n_in,
                              void* d_out, int out_size) {
    const float* X = (const float*)d_in[0];   // kv_cache fp32 (4,16,2048,128)
    float* out = (float*)d_out;               // fp32, same shape

    cudaFuncSetAttribute(jacobi_kernel, cudaFuncAttributeMaxDynamicSharedMemorySize, JAC_SMEM);
    cudaFuncSetAttribute(recon_kernel,  cudaFuncAttributeMaxDynamicSharedMemorySize, REC_SMEM);

    gram_kernel<<<dim3(NM, NPART), 256>>>(X);
    jacobi_kernel<<<dim3(2, NM), 1024, JAC_SMEM>>>();
    recon_kernel<<<dim3(NM, 32), 256, REC_SMEM>>>(X, out);
}

// round 11
// speedup vs baseline: 4.0046x; 1.0278x over previous
#include <cuda_runtime.h>
#include <math.h>
#include <stdint.h>

#define NM     64      // number of matrices (B*H)
#define MATN   128     // matrix dim (D)
#define SLEN   2048    // sequence length
#define RANK   64
#define SWEEPS 7
#define ROUNDS 127     // MATN - 1
#define TOTR   (SWEEPS * ROUNDS)
#define LDA    144     // A stride: 144 % 32 == 16 -> conflict-free (2 rows x 16 cols tiles)
#define LDW    132     // W stride: conflict-free float4 under (p + 2s) mapping
#define NPART  8       // gram split-K parts

// Scratch (device globals; no allocations allowed)
__device__ float g_G4[NPART][NM][MATN][MATN];  // partial Gram matrices (32 MB)
__device__ float g_P[NM][MATN][MATN];          // projectors (4 MB)

typedef unsigned long long u64t;
__device__ __forceinline__ u64t pack2(float lo, float hi) {
    u64t r; asm("mov.b64 %0,{%1,%2};" : "=l"(r) : "f"(lo), "f"(hi)); return r;
}
__device__ __forceinline__ u64t mul2(u64t a, u64t b) {
    u64t r; asm("mul.rn.f32x2 %0,%1,%2;" : "=l"(r) : "l"(a), "l"(b)); return r;
}
__device__ __forceinline__ u64t fma2(u64t a, u64t b, u64t c) {
    u64t r; asm("fma.rn.f32x2 %0,%1,%2,%3;" : "=l"(r) : "l"(a), "l"(b), "l"(c)); return r;
}

// ---- cluster / mbarrier helpers -------------------------------------------
__device__ __forceinline__ uint32_t ctarank() {
    uint32_t r; asm("mov.u32 %0, %%cluster_ctarank;" : "=r"(r)); return r;
}
__device__ __forceinline__ uint32_t mapa_rank(uint32_t laddr, uint32_t rank) {
    uint32_t r;
    asm("mapa.shared::cluster.u32 %0, %1, %2;" : "=r"(r) : "r"(laddr), "r"(rank));
    return r;
}
__device__ __forceinline__ void mbar_init(uint32_t a, uint32_t cnt) {
    asm volatile("mbarrier.init.shared.b64 [%0], %1;" :: "r"(a), "r"(cnt) : "memory");
}
__device__ __forceinline__ void mbar_arrive_remote(uint32_t remAddr) {
    asm volatile("mbarrier.arrive.shared::cluster.b64 _, [%0];" :: "r"(remAddr) : "memory");
}
__device__ __forceinline__ void mbar_arrive_expect_tx(uint32_t addr, uint32_t bytes) {
    asm volatile("mbarrier.arrive.expect_tx.shared::cta.b64 _, [%0], %1;"
                 :: "r"(addr), "r"(bytes) : "memory");
}
__device__ __forceinline__ void mbar_wait(uint32_t addr, uint32_t parity) {
    asm volatile(
        "{\n\t"
        ".reg .pred P;\n"
        "WAIT_%=:\n\t"
        "mbarrier.try_wait.parity.acquire.cluster.shared::cta.b64 P, [%0], %1, 0x989680;\n\t"
        "@P bra.uni DONE_%=;\n\t"
        "bra.uni WAIT_%=;\n"
        "DONE_%=:\n\t"
        "}"
        :: "r"(addr), "r"(parity) : "memory");
}
// st.async: write 16B into peer-CTA smem, tx-signaling the peer's mbarrier.
__device__ __forceinline__ void st_async_f4(uint32_t remAddr, float4 v, uint32_t remMbar) {
    asm volatile(
        "st.async.shared::cluster.mbarrier::complete_tx::bytes.v4.f32 [%0], {%1,%2,%3,%4}, [%5];"
        :: "r"(remAddr), "f"(v.x), "f"(v.y), "f"(v.z), "f"(v.w), "r"(remMbar) : "memory");
}
__device__ __forceinline__ void st_cluster_f(uint32_t addr, float v) {
    asm volatile("st.shared::cluster.f32 [%0], %1;" :: "r"(addr), "f"(v) : "memory");
}
#define CLUSTER_SYNC() do { \
    asm volatile("barrier.cluster.arrive.aligned;" ::: "memory"); \
    asm volatile("barrier.cluster.wait.aligned;" ::: "memory"); \
} while (0)

// Chess-tournament pairing: round rr in [0,127), pair index i in [0,64)
__device__ __forceinline__ void pair_pq(int i, int rr, int& p, int& q) {
    if (i == 0) { p = 0; }
    else { int x = i - 1 + rr; if (x >= 127) x -= 127; p = 1 + x; }
    int y = 126 - i + rr; if (y >= 127) y -= 127; q = 1 + y;
}

// Jacobi rotation for pair i at round rr, from A (stride LDA).
// Fast-math chain: __fdividef + MUFU rsqrt-based sqrt (u*rsqrt(u)).
// Rotations remain orthogonal to ~1e-6; error sign is random across rounds.
__device__ __forceinline__ void jac_rot(const float* A, int rr, int i,
                                        float& c, float& s, int& p, int& q) {
    pair_pq(i, rr, p, q);
    float app = A[p * LDA + p], aqq = A[q * LDA + q], apq = A[p * LDA + q];
    c = 1.f; s = 0.f;
    float scl = fabsf(app) + fabsf(aqq);
    if (fabsf(apq) > 1e-12f * scl + 1e-38f) {
        float tau = __fdividef(aqq - app, 2.f * apq);
        float u = fmaf(tau, tau, 1.f);
        float root = u * rsqrtf(u);                 // = sqrt(u), MUFU
        float tt = __fdividef(1.f, fabsf(tau) + root);
        tt = (tau < 0.f) ? -tt : tt;
        c = rsqrtf(fmaf(tt, tt, 1.f));
        s = tt * c;
    }
}

// ---------------------------------------------------------------------------
// Kernel 1: partial Gram  G_part = X_partᵀ X_part   (grid: NM x NPART, 256 thr)
// ---------------------------------------------------------------------------
__global__ __launch_bounds__(256) void gram_kernel(const float* __restrict__ X) {
    __shared__ float Xs[64][MATN];
    const int m = blockIdx.x, part = blockIdx.y;
    const int t = threadIdx.x;
    const int a0 = (t >> 4) * 8, b0 = (t & 15) * 8;
    float acc[8][8];
#pragma unroll
    for (int i = 0; i < 8; i++)
#pragma unroll
        for (int j = 0; j < 8; j++) acc[i][j] = 0.f;

    const float* Xm = X + ((size_t)m * SLEN + (size_t)part * (SLEN / NPART)) * MATN;
    for (int ch = 0; ch < SLEN / NPART / 64; ch++) {
        const float4* src = (const float4*)(Xm + (size_t)ch * 64 * MATN);
        float4* dst = (float4*)&Xs[0][0];
#pragma unroll
        for (int j = 0; j < 8; j++) dst[t + 256 * j] = src[t + 256 * j];
        __syncthreads();
#pragma unroll 4
        for (int s = 0; s < 64; s++) {
            float4 a40 = *(const float4*)&Xs[s][a0];
            float4 a41 = *(const float4*)&Xs[s][a0 + 4];
            float4 b40 = *(const float4*)&Xs[s][b0];
            float4 b41 = *(const float4*)&Xs[s][b0 + 4];
            float av[8] = {a40.x, a40.y, a40.z, a40.w, a41.x, a41.y, a41.z, a41.w};
            float bv[8] = {b40.x, b40.y, b40.z, b40.w, b41.x, b41.y, b41.z, b41.w};
#pragma unroll
            for (int i = 0; i < 8; i++)
#pragma unroll
                for (int j = 0; j < 8; j++) acc[i][j] += av[i] * bv[j];
        }
        __syncthreads();
    }
    float* Gp = &g_G4[part][m][0][0];
#pragma unroll
    for (int i = 0; i < 8; i++) {
        float4 v0 = {acc[i][0], acc[i][1], acc[i][2], acc[i][3]};
        float4 v1 = {acc[i][4], acc[i][5], acc[i][6], acc[i][7]};
        *(float4*)&Gp[(a0 + i) * MATN + b0] = v0;
        *(float4*)&Gp[(a0 + i) * MATN + b0 + 4] = v1;
    }
}

// ---------------------------------------------------------------------------
// Kernel 2: Jacobi eigensolver, 2-CTA cluster per matrix.
//   CTA rank 0: holds A; computes rotations (phase 0) + A update (phase 1a).
//   CTA rank 1: holds W = Vᵀ; applies rotations (phase 1b); builds projector.
// Rotations ship CTA0 -> CTA1 via st.async (tx-count mbarrier completion),
// double-buffered; backpressure via plain-arrive empty barriers.
// smem byte layout (identical in both CTAs):
//   [0,2048)    rot[2][64] float4
//   [2048,2064) fullb[2]  (tx mbarriers; live in CTA1)
//   [2064,2080) emptyb[2] (mbarriers; live in CTA0)
//   [2080,2592) ev[128]
//   [2592,2848) sidx[64]
//   [3072, ...) big[]: A (128x144) in CTA0 / W (128x132) in CTA1
// ---------------------------------------------------------------------------
#define BAR_FULL  2048
#define BAR_EMPTY 2064
#define EV_OFF    2080
#define SIDX_OFF  2592
#define BIG_OFF   3072
#define JAC_SMEM  (BIG_OFF + MATN * LDA * 4)

__global__ __launch_bounds__(1024) __cluster_dims__(2, 1, 1)
void jacobi_kernel() {
    extern __shared__ float smf[];
    char* smb = (char*)smf;
    float4* rot  = (float4*)smb;
    float*  ev   = (float*)(smb + EV_OFF);
    int*    sidx = (int*)(smb + SIDX_OFF);
    float*  big  = (float*)(smb + BIG_OFF);

    const int m = blockIdx.y, t = threadIdx.x;
    const uint32_t rank = ctarank();
    const uint32_t sbase = (uint32_t)__cvta_generic_to_shared(smb);

    // Init mbarriers; CTA1 pre-arms both full slots (count=1 arrive + 1024B tx)
    if (t == 0) {
        mbar_init(sbase + BAR_FULL, 1);
        mbar_init(sbase + BAR_FULL + 8, 1);
        mbar_init(sbase + BAR_EMPTY, 1);
        mbar_init(sbase + BAR_EMPTY + 8, 1);
        if (rank == 1) {
            mbar_arrive_expect_tx(sbase + BAR_FULL, 1024);
            mbar_arrive_expect_tx(sbase + BAR_FULL + 8, 1024);
        }
    }
    __syncthreads();
    CLUSTER_SYNC();   // barriers visible cluster-wide before any remote op

    const int pa  = t >> 4;   // pair index (0..63)
    const int sub = t & 15;   // sub-slot (0..15)

    if (rank == 0) {
        // ===== A-CTA =====
        // Precompute remote addresses (loop-invariant)
        const uint32_t rem_rot   = mapa_rank(sbase, 1);
        const uint32_t rem_full0 = mapa_rank(sbase + BAR_FULL, 1);
        const uint32_t rem_full1 = mapa_rank(sbase + BAR_FULL + 8, 1);

        for (int idx = t; idx < MATN * MATN; idx += 1024) {
            int i = idx >> 7, j = idx & 127;
            float a = 0.f;
#pragma unroll
            for (int pp = 0; pp < NPART; pp++) a += g_G4[pp][m][i][j];
            big[i * LDA + j] = a;
        }
        __syncthreads();

        // Prologue: rot(0) -> local slot0 + remote slot0 (st.async, tx-signal)
        if (t < 64) {
            float c, s; int p, q;
            jac_rot(big, 0, t, c, s, p, q);
            float4 v = make_float4(c, s, __int_as_float(p), __int_as_float(q));
            rot[t] = v;
            st_async_f4(rem_rot + t * 16, v, rem_full0);
        }
        __syncthreads();

        int phE0 = 0, phE1 = 1;   // producer empty-parity per slot (slot1 first wait passes)

        for (int r = 0; r < TOTR; r++) {
            // Early empty-wait for NEXT round's slot: CTA1 released it a full
            // round ago, so this is a fast-path wait hidden under 1a issue.
            if (t < 64 && r + 1 < TOTR) {
                int s_n = (r + 1) & 1;
                int par = s_n ? phE1 : phE0;
                mbar_wait(sbase + BAR_EMPTY + s_n * 8, par);
                if (s_n) phE1 ^= 1; else phE0 ^= 1;
            }

            float4* rots = rot + ((r & 1) << 6);
            float4 ra = rots[pa];
            const float ca = ra.x, sa = ra.y;
            const int p_a = __float_as_int(ra.z), q_a = __float_as_int(ra.w);
            float* Arp = big + p_a * LDA;
            float* Arq = big + q_a * LDA;

            // Phase 1a: fused 2x2 closure-block update A' = JᵀAJ (all scalar)
#pragma unroll
            for (int k = 0; k < 4; k++) {
                int bp = sub + (k << 4);
                float4 rb = rots[bp];
                float cb = rb.x, sb = rb.y;
                int p_b = __float_as_int(rb.z), q_b = __float_as_int(rb.w);
                float m00 = Arp[p_b], m01 = Arp[q_b];
                float m10 = Arq[p_b], m11 = Arq[q_b];
                float r00 = ca * m00 - sa * m10, r01 = ca * m01 - sa * m11;
                float r10 = sa * m00 + ca * m10, r11 = sa * m01 + ca * m11;
                Arp[p_b] = cb * r00 - sb * r01;
                Arp[q_b] = sb * r00 + cb * r01;
                Arq[p_b] = cb * r10 - sb * r11;
                Arq[q_b] = sb * r10 + cb * r11;
            }
            __syncthreads();

            if (r + 1 < TOTR) {
                int s = (r + 1) & 1;
                if (t < 64) {
                    float c, sn; int p, q;
                    int rr1 = r + 1; rr1 -= (rr1 / ROUNDS) * ROUNDS;
                    jac_rot(big, rr1, t, c, sn, p, q);
                    float4 v = make_float4(c, sn, __int_as_float(p), __int_as_float(q));
                    rot[(s << 6) + t] = v;
                    st_async_f4(rem_rot + ((s << 6) + t) * 16, v,
                                s ? rem_full1 : rem_full0);
                }
                __syncthreads();   // local rot slot visible to next round's 1a
            }
        }

        // Ship eigenvalue diagonal to CTA1
        if (t < MATN) {
            float e = big[t * LDA + t];
            st_cluster_f(mapa_rank(sbase + EV_OFF + t * 4, 1), e);
        }
        CLUSTER_SYNC();   // arrive.release publishes ev; CTA1's wait acquires
    } else {
        // ===== W-CTA =====
        for (int idx = t; idx < MATN * MATN; idx += 1024) {
            int i = idx >> 7, j = idx & 127;
            big[i * LDW + j] = (i == j) ? 1.f : 0.f;
        }
        __syncthreads();

        int phF0 = 0, phF1 = 0;   // consumer full-parity per slot

        for (int r = 0; r < TOTR; r++) {
            int s = r & 1;
            {
                int par = s ? phF1 : phF0;
                mbar_wait(sbase + BAR_FULL + s * 8, par);   // ALL threads
                if (s) phF1 ^= 1; else phF0 ^= 1;
            }
            if (t == 0)   // re-arm this slot for its next use (phase already flipped)
                mbar_arrive_expect_tx(sbase + BAR_FULL + s * 8, 1024);

            float4 ra = rot[(s << 6) + pa];
            __syncthreads();   // all rot reads done before releasing the slot
            if (t == 0) mbar_arrive_remote(mapa_rank(sbase + BAR_EMPTY + s * 8, 0));

            const float ca = ra.x, sa = ra.y;
            const int p_a = __float_as_int(ra.z), q_a = __float_as_int(ra.w);

            // Phase 1b: W = Vᵀ row rotation, packed f32x2 (8 cols per thread)
            ulonglong2* Wp = (ulonglong2*)(big + p_a * LDW + (sub << 3));
            ulonglong2* Wq = (ulonglong2*)(big + q_a * LDW + (sub << 3));
            const u64t ca2  = pack2(ca, ca);
            const u64t sa2  = pack2(sa, sa);
            const u64t nsa2 = pack2(-sa, -sa);
#pragma unroll
            for (int i = 0; i < 2; i++) {
                ulonglong2 x = Wp[i], y = Wq[i];
                ulonglong2 nx, ny;
                nx.x = fma2(ca2, x.x, mul2(nsa2, y.x));
                nx.y = fma2(ca2, x.y, mul2(nsa2, y.y));
                ny.x = fma2(sa2, x.x, mul2(ca2, y.x));
                ny.y = fma2(sa2, x.y, mul2(ca2, y.y));
                Wp[i] = nx; Wq[i] = ny;
            }
            // no trailing bar: next round's wait orders 1b(r) before 1b(r+1)
        }

        CLUSTER_SYNC();   // ev now visible locally

        // Top-RANK selection (tie-break by index -> deterministic)
        if (t < MATN) {
            float e = ev[t]; int rk = 0;
            for (int j = 0; j < MATN; j++) {
                float o = ev[j];
                if (o > e || (o == e && j < t)) rk++;
            }
            if (rk < RANK) sidx[rk] = t;
        }
        __syncthreads();

        // P = Σ over 64 selected rows of W: W[r,:]ᵀ W[r,:]
        const int i0 = (t >> 5) * 4, j0 = (t & 31) * 4;
        float acc[4][4];
#pragma unroll
        for (int i = 0; i < 4; i++)
#pragma unroll
            for (int j = 0; j < 4; j++) acc[i][j] = 0.f;

        for (int ii = 0; ii < RANK; ii++) {
            int row = sidx[ii];
            const float* Wr = big + row * LDW;
            float4 va4 = *(const float4*)&Wr[i0];
            float4 vb4 = *(const float4*)&Wr[j0];
            float va[4] = {va4.x, va4.y, va4.z, va4.w};
            float vb[4] = {vb4.x, vb4.y, vb4.z, vb4.w};
#pragma unroll
            for (int i = 0; i < 4; i++)
#pragma unroll
                for (int j = 0; j < 4; j++) acc[i][j] += va[i] * vb[j];
        }
        float* Pp = &g_P[m][0][0];
#pragma unroll
        for (int i = 0; i < 4; i++) {
            float4 v = {acc[i][0], acc[i][1], acc[i][2], acc[i][3]};
            *(float4*)&Pp[(i0 + i) * MATN + j0] = v;
        }
    }
}

// ---------------------------------------------------------------------------
// Kernel 3: Y = X · P  (grid: NM x 32 row-blocks of 64 rows, 256 threads)
// ---------------------------------------------------------------------------
#define LDX 129
#define REC_SMEM ((64 * LDX + MATN * MATN) * 4)

__global__ __launch_bounds__(256) void recon_kernel(const float* __restrict__ X,
                                                    float* __restrict__ out) {
    extern __shared__ float sm[];
    float* Xs = sm;              // 64 x 129
    float* Ps = sm + 64 * LDX;   // 128 x 128
    const int m = blockIdx.x, rb = blockIdx.y;
    const int t = threadIdx.x;

    const float* Xm = X + ((size_t)m * SLEN + (size_t)rb * 64) * MATN;
    for (int idx = t; idx < 64 * MATN; idx += 256) {
        int rI = idx >> 7, c = idx & 127;
        Xs[rI * LDX + c] = Xm[idx];
    }
    const float4* Pg = (const float4*)&g_P[m][0][0];
    float4* Pd = (float4*)Ps;
    for (int idx = t; idx < MATN * MATN / 4; idx += 256) Pd[idx] = Pg[idx];
    __syncthreads();

    const int r0 = (t >> 4) * 4, c0 = (t & 15) * 8;
    float acc[4][8];
#pragma unroll
    for (int i = 0; i < 4; i++)
#pragma unroll
        for (int j = 0; j < 8; j++) acc[i][j] = 0.f;

    for (int k = 0; k < MATN; k++) {
        float xv[4];
#pragma unroll
        for (int i = 0; i < 4; i++) xv[i] = Xs[(r0 + i) * LDX + k];
        float4 p0 = *(const float4*)&Ps[k * MATN + c0];
        float4 p1 = *(const float4*)&Ps[k * MATN + c0 + 4];
        float pv[8] = {p0.x, p0.y, p0.z, p0.w, p1.x, p1.y, p1.z, p1.w};
#pragma unroll
        for (int i = 0; i < 4; i++)
#pragma unroll
            for (int j = 0; j < 8; j++) acc[i][j] += xv[i] * pv[j];
    }

    float* Om = out + ((size_t)m * SLEN + (size_t)rb * 64) * MATN;
#pragma unroll
    for (int i = 0; i < 4; i++) {
        float4 v0 = {acc[i][0], acc[i][1], acc[i][2], acc[i][3]};
        float4 v1 = {acc[i][4], acc[i][5], acc[i][6], acc[i][7]};
        *(float4*)&Om[(r0 + i) * MATN + c0] = v0;
        *(float4*)&Om[(r0 + i) * MATN + c0 + 4] = v1;
    }
}

// ---------------------------------------------------------------------------
extern "C" void kernel_launch(void* const* d_in, const int* in_sizes, int n_in,
                              void* d_out, int out_size) {
    const float* X = (const float*)d_in[0];   // kv_cache fp32 (4,16,2048,128)
    float* out = (float*)d_out;               // fp32, same shape

    cudaFuncSetAttribute(jacobi_kernel, cudaFuncAttributeMaxDynamicSharedMemorySize, JAC_SMEM);
    cudaFuncSetAttribute(recon_kernel,  cudaFuncAttributeMaxDynamicSharedMemorySize, REC_SMEM);

    gram_kernel<<<dim3(NM, NPART), 256>>>(X);
    jacobi_kernel<<<dim3(2, NM), 1024, JAC_SMEM>>>();
    recon_kernel<<<dim3(NM, 32), 256, REC_SMEM>>>(X, out);
}